// round 2
// baseline (speedup 1.0000x reference)
#include <cuda_runtime.h>
#include <cstdint>

// ---------------- problem constants ----------------
#define Nn_NODES 16384      // B*L
#define Dm 256              // d_model
#define Hh 4                // heads
#define Cc 256              // per-head channels
#define HD (Hh*Cc)          // 1024
#define Ee 65536            // edges (self loops handled separately)
#define NEG_SLOPE 0.2f
#define LN_EPS 1e-6f

// ---------------- device scratch (static, no allocation) ----------------
__device__ float    g_xln   [Nn_NODES * Dm];
__device__ float    g_gnn_in[Nn_NODES * Dm];
__device__ float    g_xh    [Nn_NODES * HD];
__device__ float    g_asrc  [Nn_NODES * Hh];
__device__ float    g_adst  [Nn_NODES * Hh];
__device__ unsigned g_emax  [Nn_NODES * Hh];
__device__ float    g_denom [Nn_NODES * Hh];
__device__ float    g_agg   [Nn_NODES * Dm];

// ---------------- helpers ----------------
__device__ __forceinline__ float leaky(float x) {
    return x > 0.0f ? x : NEG_SLOPE * x;
}
// order-preserving float <-> uint for atomicMax on floats (handles negatives)
__device__ __forceinline__ unsigned f2o(float f) {
    unsigned u = __float_as_uint(f);
    return (u & 0x80000000u) ? ~u : (u | 0x80000000u);
}
__device__ __forceinline__ float o2f(unsigned u) {
    return (u & 0x80000000u) ? __uint_as_float(u & 0x7FFFFFFFu)
                             : __uint_as_float(~u);
}
__device__ __forceinline__ float warp_sum(float v) {
    #pragma unroll
    for (int o = 16; o > 0; o >>= 1) v += __shfl_xor_sync(0xFFFFFFFFu, v, o);
    return v;
}

// ---------------- 1) LayerNorm ----------------
__global__ __launch_bounds__(256) void ln_kernel(
    const float* __restrict__ x, const float* __restrict__ gamma,
    const float* __restrict__ beta)
{
    int n = blockIdx.x;
    int t = threadIdx.x;
    float v = x[(size_t)n * Dm + t];

    __shared__ float red[8];
    __shared__ float s_mu, s_rstd;

    float s = warp_sum(v);
    if ((t & 31) == 0) red[t >> 5] = s;
    __syncthreads();
    if (t == 0) {
        float tot = 0.f;
        #pragma unroll
        for (int i = 0; i < 8; i++) tot += red[i];
        s_mu = tot * (1.0f / Dm);
    }
    __syncthreads();
    float d = v - s_mu;
    float s2 = warp_sum(d * d);
    if ((t & 31) == 0) red[t >> 5] = s2;
    __syncthreads();
    if (t == 0) {
        float tot = 0.f;
        #pragma unroll
        for (int i = 0; i < 8; i++) tot += red[i];
        s_rstd = rsqrtf(tot * (1.0f / Dm) + LN_EPS);
    }
    __syncthreads();
    g_xln[(size_t)n * Dm + t] = d * s_rstd * gamma[t] + beta[t];
}

// ---------------- 2) SGEMM:  C[M,N] = (A + a_kbias) * B^T (+c_bias)(+resid) ----
// A [M,K] row-major, B [N,K] row-major. BM=BN=128, BK=16, 256 thr, 8x8/thread.
#define BM 128
#define BN 128
#define BK 16
__global__ __launch_bounds__(256) void sgemm_nt(
    const float* __restrict__ A, const float* __restrict__ B,
    float* __restrict__ C, int M, int N, int K,
    const float* __restrict__ a_kbias,   // [K] or nullptr (added to A columns)
    const float* __restrict__ c_bias,    // [N] or nullptr
    const float* __restrict__ resid)     // [M*N] or nullptr
{
    __shared__ float As[BK][BM];
    __shared__ float Bs[BK][BN];

    int tid  = threadIdx.x;
    int brow = blockIdx.y, bcol = blockIdx.x;
    int trow = tid >> 4, tcol = tid & 15;     // 16x16 thread grid

    float acc[8][8];
    #pragma unroll
    for (int i = 0; i < 8; i++)
        #pragma unroll
        for (int j = 0; j < 8; j++) acc[i][j] = 0.f;

    int lrow = tid >> 2;            // 0..63
    int lcol = (tid & 3) << 2;      // 0,4,8,12

    const float* Ab = A + (size_t)brow * BM * K;
    const float* Bb = B + (size_t)bcol * BN * K;

    for (int k0 = 0; k0 < K; k0 += BK) {
        #pragma unroll
        for (int r = 0; r < 2; ++r) {
            int m = lrow + r * 64;
            float4 va = *(const float4*)(Ab + (size_t)m * K + k0 + lcol);
            if (a_kbias) {
                va.x += a_kbias[k0 + lcol + 0];
                va.y += a_kbias[k0 + lcol + 1];
                va.z += a_kbias[k0 + lcol + 2];
                va.w += a_kbias[k0 + lcol + 3];
            }
            As[lcol + 0][m] = va.x; As[lcol + 1][m] = va.y;
            As[lcol + 2][m] = va.z; As[lcol + 3][m] = va.w;

            float4 vb = *(const float4*)(Bb + (size_t)m * K + k0 + lcol);
            Bs[lcol + 0][m] = vb.x; Bs[lcol + 1][m] = vb.y;
            Bs[lcol + 2][m] = vb.z; Bs[lcol + 3][m] = vb.w;
        }
        __syncthreads();

        #pragma unroll
        for (int k = 0; k < BK; ++k) {
            float ra[8], rb[8];
            *(float4*)&ra[0] = *(const float4*)&As[k][trow * 8];
            *(float4*)&ra[4] = *(const float4*)&As[k][trow * 8 + 4];
            *(float4*)&rb[0] = *(const float4*)&Bs[k][tcol * 8];
            *(float4*)&rb[4] = *(const float4*)&Bs[k][tcol * 8 + 4];
            #pragma unroll
            for (int i = 0; i < 8; i++)
                #pragma unroll
                for (int j = 0; j < 8; j++)
                    acc[i][j] = fmaf(ra[i], rb[j], acc[i][j]);
        }
        __syncthreads();
    }

    #pragma unroll
    for (int i = 0; i < 8; i++) {
        int row = brow * BM + trow * 8 + i;
        #pragma unroll
        for (int j = 0; j < 8; j++) {
            int col = bcol * BN + tcol * 8 + j;
            float v = acc[i][j];
            if (c_bias) v += c_bias[col];
            if (resid)  v += resid[(size_t)row * N + col];
            C[(size_t)row * N + col] = v;
        }
    }
}

// ---------------- 3) attention dots: a_src/a_dst [N,H] ----------------
__global__ __launch_bounds__(128) void att_dot_kernel(
    const float* __restrict__ att_src, const float* __restrict__ att_dst)
{
    int n = blockIdx.x;
    int h = threadIdx.x >> 5;
    int lane = threadIdx.x & 31;
    const float* xr = g_xh + (size_t)n * HD + h * Cc;
    float s = 0.f, d = 0.f;
    #pragma unroll
    for (int i = 0; i < 8; i++) {
        int c = lane + 32 * i;
        float x = xr[c];
        s = fmaf(x, att_src[h * Cc + c], s);
        d = fmaf(x, att_dst[h * Cc + c], d);
    }
    s = warp_sum(s);
    d = warp_sum(d);
    if (lane == 0) {
        g_asrc[n * Hh + h] = s;
        g_adst[n * Hh + h] = d;
    }
}

// ---------------- 4) softmax passes (edge indices are INT32) ----------------
__global__ __launch_bounds__(256) void init_max_kernel() {
    int idx = blockIdx.x * 256 + threadIdx.x;           // < N*H
    float v = leaky(g_asrc[idx] + g_adst[idx]);         // self loop
    g_emax[idx] = f2o(v);
}

__global__ __launch_bounds__(256) void edge_max_kernel(
    const int* __restrict__ esrc, const int* __restrict__ edst)
{
    int idx = blockIdx.x * 256 + threadIdx.x;           // < E*H
    int e = idx >> 2, h = idx & 3;
    int s = esrc[e], d = edst[e];
    float v = leaky(g_asrc[s * Hh + h] + g_adst[d * Hh + h]);
    atomicMax(&g_emax[d * Hh + h], f2o(v));
}

__global__ __launch_bounds__(256) void init_denom_kernel() {
    int idx = blockIdx.x * 256 + threadIdx.x;           // < N*H
    float self = leaky(g_asrc[idx] + g_adst[idx]);
    g_denom[idx] = expf(self - o2f(g_emax[idx]));
}

__global__ __launch_bounds__(256) void edge_denom_kernel(
    const int* __restrict__ esrc, const int* __restrict__ edst)
{
    int idx = blockIdx.x * 256 + threadIdx.x;           // < E*H
    int e = idx >> 2, h = idx & 3;
    int s = esrc[e], d = edst[e];
    float v = leaky(g_asrc[s * Hh + h] + g_adst[d * Hh + h]);
    atomicAdd(&g_denom[d * Hh + h], expf(v - o2f(g_emax[d * Hh + h])));
}

// ---------------- 5) aggregation (head-mean folded into scatter) ----------
__global__ __launch_bounds__(256) void self_agg_kernel() {
    int n = blockIdx.x, t = threadIdx.x;
    __shared__ float w[Hh];
    if (t < Hh) {
        float self = leaky(g_asrc[n * Hh + t] + g_adst[n * Hh + t]);
        w[t] = expf(self - o2f(g_emax[n * Hh + t])) / g_denom[n * Hh + t]
               * (1.0f / Hh);
    }
    __syncthreads();
    const float* xr = g_xh + (size_t)n * HD;
    float acc = 0.f;
    #pragma unroll
    for (int h = 0; h < Hh; h++) acc = fmaf(w[h], xr[h * Cc + t], acc);
    g_agg[(size_t)n * Dm + t] = acc;
}

__global__ __launch_bounds__(256) void edge_agg_kernel(
    const int* __restrict__ esrc, const int* __restrict__ edst)
{
    int e = blockIdx.x, t = threadIdx.x;
    __shared__ float w[Hh];
    __shared__ int sh_s, sh_d;
    if (t == 0) { sh_s = esrc[e]; sh_d = edst[e]; }
    if (t < Hh) {
        int s = esrc[e], d = edst[e];
        float v = leaky(g_asrc[s * Hh + t] + g_adst[d * Hh + t]);
        w[t] = expf(v - o2f(g_emax[d * Hh + t])) / g_denom[d * Hh + t]
               * (1.0f / Hh);
    }
    __syncthreads();
    const float* xr = g_xh + (size_t)sh_s * HD;
    float acc = 0.f;
    #pragma unroll
    for (int h = 0; h < Hh; h++) acc = fmaf(w[h], xr[h * Cc + t], acc);
    atomicAdd(&g_agg[(size_t)sh_d * Dm + t], acc);
}

// ---------------- launch ----------------
extern "C" void kernel_launch(void* const* d_in, const int* in_sizes, int n_in,
                              void* d_out, int out_size)
{
    const float* inputs   = (const float*)d_in[0];
    const int*   eidx     = (const int*)d_in[1];      // int32 (JAX x64 disabled)
    const float* ln_gamma = (const float*)d_in[2];
    const float* ln_beta  = (const float*)d_in[3];
    const float* W1       = (const float*)d_in[4];
    const float* b1       = (const float*)d_in[5];
    const float* W_gat    = (const float*)d_in[6];
    const float* att_src  = (const float*)d_in[7];
    const float* att_dst  = (const float*)d_in[8];
    const float* bias_gat = (const float*)d_in[9];
    const float* W2       = (const float*)d_in[10];
    const float* b2       = (const float*)d_in[11];
    float*       out      = (float*)d_out;

    const int* esrc = eidx;
    const int* edst = eidx + Ee;

    float* xln;    cudaGetSymbolAddress((void**)&xln,    g_xln);
    float* gnn_in; cudaGetSymbolAddress((void**)&gnn_in, g_gnn_in);
    float* xh;     cudaGetSymbolAddress((void**)&xh,     g_xh);
    float* agg;    cudaGetSymbolAddress((void**)&agg,    g_agg);

    // 1) LayerNorm
    ln_kernel<<<Nn_NODES, 256>>>(inputs, ln_gamma, ln_beta);

    // 2) gnn_in = xln @ W1^T + b1
    sgemm_nt<<<dim3(Dm / BN, Nn_NODES / BM), 256>>>(
        xln, W1, gnn_in, Nn_NODES, Dm, Dm, nullptr, b1, nullptr);

    // 3) xh = gnn_in @ W_gat^T
    sgemm_nt<<<dim3(HD / BN, Nn_NODES / BM), 256>>>(
        gnn_in, W_gat, xh, Nn_NODES, HD, Dm, nullptr, nullptr, nullptr);

    // 4) attention dots
    att_dot_kernel<<<Nn_NODES, 128>>>(att_src, att_dst);

    // 5) segment softmax
    init_max_kernel<<<(Nn_NODES * Hh) / 256, 256>>>();
    edge_max_kernel<<<(Ee * Hh) / 256, 256>>>(esrc, edst);
    init_denom_kernel<<<(Nn_NODES * Hh) / 256, 256>>>();
    edge_denom_kernel<<<(Ee * Hh) / 256, 256>>>(esrc, edst);

    // 6) aggregation (self loops init, edges atomically accumulate)
    self_agg_kernel<<<Nn_NODES, 256>>>();
    edge_agg_kernel<<<Ee, 256>>>(esrc, edst);

    // 7) out = (agg + bias_gat) @ W2^T + b2 + inputs
    sgemm_nt<<<dim3(Dm / BN, Nn_NODES / BM), 256>>>(
        agg, W2, out, Nn_NODES, Dm, Dm, bias_gat, b2, inputs);
}

// round 4
// speedup vs baseline: 1.8119x; 1.8119x over previous
#include <cuda_runtime.h>
#include <cuda_bf16.h>
#include <cstdint>

// ---------------- problem constants ----------------
#define Nn_NODES 16384      // B*L
#define Dm 256              // d_model
#define Hh 4                // heads
#define Cc 256              // per-head channels
#define HD (Hh*Cc)          // 1024
#define Ee 65536            // edges
#define NEG_SLOPE 0.2f
#define LN_EPS 1e-6f

// ---------------- device scratch ----------------
__device__ __nv_bfloat16 g_xln_hi[Nn_NODES * Dm];
__device__ __nv_bfloat16 g_xln_lo[Nn_NODES * Dm];
__device__ __nv_bfloat16 g_gnn_hi[Nn_NODES * Dm];
__device__ __nv_bfloat16 g_gnn_lo[Nn_NODES * Dm];
__device__ __nv_bfloat16 g_agg_hi[Nn_NODES * Dm];
__device__ __nv_bfloat16 g_agg_lo[Nn_NODES * Dm];
__device__ __nv_bfloat16 g_w1_hi[Dm * Dm],  g_w1_lo[Dm * Dm];
__device__ __nv_bfloat16 g_wg_hi[HD * Dm],  g_wg_lo[HD * Dm];
__device__ __nv_bfloat16 g_w2_hi[Dm * Dm],  g_w2_lo[Dm * Dm];
__device__ float    g_xh   [Nn_NODES * HD];
__device__ float    g_agg  [Nn_NODES * Dm];
__device__ float    g_asrc [Nn_NODES * Hh];
__device__ float    g_adst [Nn_NODES * Hh];
__device__ unsigned g_emax [Nn_NODES * Hh];
__device__ float    g_denom[Nn_NODES * Hh];

// ---------------- helpers ----------------
__device__ __forceinline__ float leaky(float x) { return x > 0.0f ? x : NEG_SLOPE * x; }
__device__ __forceinline__ unsigned f2o(float f) {
    unsigned u = __float_as_uint(f);
    return (u & 0x80000000u) ? ~u : (u | 0x80000000u);
}
__device__ __forceinline__ float o2f(unsigned u) {
    return (u & 0x80000000u) ? __uint_as_float(u & 0x7FFFFFFFu) : __uint_as_float(~u);
}
__device__ __forceinline__ float warp_sum(float v) {
    #pragma unroll
    for (int o = 16; o > 0; o >>= 1) v += __shfl_xor_sync(0xFFFFFFFFu, v, o);
    return v;
}
__device__ __forceinline__ void split2(float v, __nv_bfloat16& h, __nv_bfloat16& l) {
    h = __float2bfloat16(v);
    l = __float2bfloat16(v - __bfloat162float(h));
}
__device__ __forceinline__ uint32_t smem_to_u32(const void* p) {
    uint32_t a;
    asm("{ .reg .u64 t; cvta.to.shared.u64 t, %1; cvt.u32.u64 %0, t; }"
        : "=r"(a) : "l"(p));
    return a;
}

// ---------------- mma / ldmatrix / cp.async PTX (sm_80-compatible) --------
#define LDM4(r, addr) \
    asm volatile("ldmatrix.sync.aligned.m8n8.x4.shared.b16 {%0,%1,%2,%3}, [%4];" \
        : "=r"((r)[0]), "=r"((r)[1]), "=r"((r)[2]), "=r"((r)[3]) : "r"(addr))

#define MMA_BF16(c, a, b0, b1) \
    asm volatile("mma.sync.aligned.m16n8k16.row.col.f32.bf16.bf16.f32 " \
        "{%0,%1,%2,%3}, {%4,%5,%6,%7}, {%8,%9}, {%0,%1,%2,%3};" \
        : "+f"((c)[0]), "+f"((c)[1]), "+f"((c)[2]), "+f"((c)[3]) \
        : "r"((a)[0]), "r"((a)[1]), "r"((a)[2]), "r"((a)[3]), "r"(b0), "r"(b1))

#define CP_ASYNC16(dst, src) \
    asm volatile("cp.async.cg.shared.global [%0], [%1], 16;" \
        :: "r"(dst), "l"(src) : "memory")
#define CP_COMMIT() asm volatile("cp.async.commit_group;" ::: "memory")
#define CP_WAIT1()  asm volatile("cp.async.wait_group 1;" ::: "memory")
#define CP_WAIT0()  asm volatile("cp.async.wait_group 0;" ::: "memory")

// ---------------- split kernel: fp32 -> bf16 hi/lo (optional col bias) -----
__global__ __launch_bounds__(256) void split_kernel(
    const float* __restrict__ src, __nv_bfloat16* __restrict__ hi,
    __nv_bfloat16* __restrict__ lo, const float* __restrict__ bias, int colmask)
{
    int i = blockIdx.x * 256 + threadIdx.x;
    float v = src[i];
    if (bias) v += bias[i & colmask];
    split2(v, hi[i], lo[i]);
}

// ---------------- LayerNorm -> bf16 hi/lo ----------------
__global__ __launch_bounds__(256) void ln_kernel(
    const float* __restrict__ x, const float* __restrict__ gamma,
    const float* __restrict__ beta)
{
    int n = blockIdx.x, t = threadIdx.x;
    float v = x[(size_t)n * Dm + t];
    __shared__ float red[8];
    __shared__ float s_mu, s_rstd;
    float s = warp_sum(v);
    if ((t & 31) == 0) red[t >> 5] = s;
    __syncthreads();
    if (t == 0) {
        float tot = 0.f;
        #pragma unroll
        for (int i = 0; i < 8; i++) tot += red[i];
        s_mu = tot * (1.0f / Dm);
    }
    __syncthreads();
    float d = v - s_mu;
    float s2 = warp_sum(d * d);
    if ((t & 31) == 0) red[t >> 5] = s2;
    __syncthreads();
    if (t == 0) {
        float tot = 0.f;
        #pragma unroll
        for (int i = 0; i < 8; i++) tot += red[i];
        s_rstd = rsqrtf(tot * (1.0f / Dm) + LN_EPS);
    }
    __syncthreads();
    float o = d * s_rstd * gamma[t] + beta[t];
    split2(o, g_xln_hi[(size_t)n * Dm + t], g_xln_lo[(size_t)n * Dm + t]);
}

// ---------------- bf16x3 HMMA GEMM ----------------
// C[M,Ncols] = A[M,256] @ B[Ncols,256]^T, tiles 128x128, K=256 in 4 chunks of 64.
// SMEM per stage: Ahi, Alo, Bhi, Blo each [128][64] bf16 (128B rows, SW128 swizzle).
#define ST_STRIDE 65536
#define O_AH 0
#define O_AL 16384
#define O_BH 32768
#define O_BL 49152
#define GEMM_SMEM (2 * ST_STRIDE)

__global__ __launch_bounds__(256) void gemm_mma(
    const __nv_bfloat16* __restrict__ Ahi, const __nv_bfloat16* __restrict__ Alo,
    const __nv_bfloat16* __restrict__ Bhi, const __nv_bfloat16* __restrict__ Blo,
    int Ncols, const float* __restrict__ c_bias, const float* __restrict__ resid,
    float* __restrict__ Cf32, __nv_bfloat16* __restrict__ Chi,
    __nv_bfloat16* __restrict__ Clo)
{
    extern __shared__ char smem[];
    uint32_t sb = smem_to_u32(smem);
    const int tid = threadIdx.x, lane = tid & 31, wid = tid >> 5;
    const int warp_m0 = (wid >> 2) * 64;     // 2 warps in M
    const int warp_n0 = (wid & 3) * 32;      // 4 warps in N
    const size_t m0 = (size_t)blockIdx.y * 128;
    const size_t n0 = (size_t)blockIdx.x * 128;

    float acc[4][4][4];
    #pragma unroll
    for (int i = 0; i < 4; i++)
        #pragma unroll
        for (int j = 0; j < 4; j++)
            #pragma unroll
            for (int k = 0; k < 4; k++) acc[i][j][k] = 0.f;

    // lane-invariant fragment addressing
    const int arow = lane & 15;
    const int akb  = (lane >> 4) << 4;                 // 0 or 16 bytes (k halves)
    const int brl  = ((lane >> 4) << 3) | (lane & 7);  // n row within 16-group
    const int bkb  = ((lane >> 3) & 1) << 4;
    const uint32_t aswz = (uint32_t)(arow & 7) << 4;
    const uint32_t bswz = (uint32_t)(lane & 7) << 4;

    auto issue = [&](int stage, int kc0) {
        uint32_t s0 = sb + stage * ST_STRIDE;
        #pragma unroll
        for (int it = 0; it < 4; ++it) {
            int idx = tid + it * 256;
            int row = idx >> 3, c16 = idx & 7;
            uint32_t off = (uint32_t)row * 128 + c16 * 16;
            off ^= ((uint32_t)(row & 7)) << 4;           // SW128
            size_t gA = (m0 + row) * 256 + kc0 + c16 * 8;
            size_t gB = (n0 + row) * 256 + kc0 + c16 * 8;
            CP_ASYNC16(s0 + O_AH + off, Ahi + gA);
            CP_ASYNC16(s0 + O_AL + off, Alo + gA);
            CP_ASYNC16(s0 + O_BH + off, Bhi + gB);
            CP_ASYNC16(s0 + O_BL + off, Blo + gB);
        }
    };

    issue(0, 0);
    CP_COMMIT();

    for (int kc = 0; kc < 4; ++kc) {
        if (kc < 3) {
            issue((kc + 1) & 1, (kc + 1) * 64);
            CP_COMMIT();
            CP_WAIT1();
        } else {
            CP_WAIT0();
        }
        __syncthreads();

        uint32_t st = sb + (kc & 1) * ST_STRIDE;
        #pragma unroll
        for (int k16 = 0; k16 < 4; ++k16) {
            int kbyte = k16 * 32;
            uint32_t ah[4][4], al[4][4], bh[2][4], bl[2][4];
            #pragma unroll
            for (int mt = 0; mt < 4; ++mt) {
                uint32_t ad = st + O_AH +
                    (uint32_t)(warp_m0 + mt * 16 + arow) * 128 + kbyte + akb;
                LDM4(ah[mt], ad ^ aswz);
                LDM4(al[mt], (ad + (O_AL - O_AH)) ^ aswz);
            }
            #pragma unroll
            for (int g2 = 0; g2 < 2; ++g2) {
                uint32_t bd = st + O_BH +
                    (uint32_t)(warp_n0 + g2 * 16 + brl) * 128 + kbyte + bkb;
                LDM4(bh[g2], bd ^ bswz);
                LDM4(bl[g2], (bd + (O_BL - O_BH)) ^ bswz);
            }
            #pragma unroll
            for (int mt = 0; mt < 4; ++mt)
                #pragma unroll
                for (int nt = 0; nt < 4; ++nt) {
                    int g2 = nt >> 1, p = (nt & 1) << 1;
                    MMA_BF16(acc[mt][nt], ah[mt], bh[g2][p], bh[g2][p + 1]);
                    MMA_BF16(acc[mt][nt], ah[mt], bl[g2][p], bl[g2][p + 1]);
                    MMA_BF16(acc[mt][nt], al[mt], bh[g2][p], bh[g2][p + 1]);
                }
        }
        __syncthreads();
    }

    // epilogue
    const int g = lane >> 2, tq = lane & 3;
    #pragma unroll
    for (int mt = 0; mt < 4; ++mt) {
        #pragma unroll
        for (int nt = 0; nt < 4; ++nt) {
            size_t r = m0 + warp_m0 + mt * 16 + g;
            size_t c = n0 + warp_n0 + nt * 8 + tq * 2;
            float v00 = acc[mt][nt][0], v01 = acc[mt][nt][1];
            float v10 = acc[mt][nt][2], v11 = acc[mt][nt][3];
            if (c_bias) {
                float cb0 = c_bias[c], cb1 = c_bias[c + 1];
                v00 += cb0; v01 += cb1; v10 += cb0; v11 += cb1;
            }
            size_t o0 = r * (size_t)Ncols + c;
            size_t o1 = (r + 8) * (size_t)Ncols + c;
            if (resid) {
                v00 += resid[o0]; v01 += resid[o0 + 1];
                v10 += resid[o1]; v11 += resid[o1 + 1];
            }
            if (Cf32) {
                *(float2*)(Cf32 + o0) = make_float2(v00, v01);
                *(float2*)(Cf32 + o1) = make_float2(v10, v11);
            }
            if (Chi) {
                split2(v00, Chi[o0], Clo[o0]);
                split2(v01, Chi[o0 + 1], Clo[o0 + 1]);
                split2(v10, Chi[o1], Clo[o1]);
                split2(v11, Chi[o1 + 1], Clo[o1 + 1]);
            }
        }
    }
}

// ---------------- attention dots ----------------
__global__ __launch_bounds__(128) void att_dot_kernel(
    const float* __restrict__ att_src, const float* __restrict__ att_dst)
{
    int n = blockIdx.x;
    int h = threadIdx.x >> 5;
    int lane = threadIdx.x & 31;
    const float* xr = g_xh + (size_t)n * HD + h * Cc;
    float s = 0.f, d = 0.f;
    #pragma unroll
    for (int i = 0; i < 8; i++) {
        int c = lane + 32 * i;
        float x = xr[c];
        s = fmaf(x, att_src[h * Cc + c], s);
        d = fmaf(x, att_dst[h * Cc + c], d);
    }
    s = warp_sum(s);
    d = warp_sum(d);
    if (lane == 0) { g_asrc[n * Hh + h] = s; g_adst[n * Hh + h] = d; }
}

// ---------------- softmax passes ----------------
__global__ __launch_bounds__(256) void init_max_kernel() {
    int idx = blockIdx.x * 256 + threadIdx.x;
    float v = leaky(g_asrc[idx] + g_adst[idx]);
    g_emax[idx] = f2o(v);
}
__global__ __launch_bounds__(256) void edge_max_kernel(
    const int* __restrict__ esrc, const int* __restrict__ edst)
{
    int idx = blockIdx.x * 256 + threadIdx.x;
    int e = idx >> 2, h = idx & 3;
    int s = esrc[e], d = edst[e];
    float v = leaky(g_asrc[s * Hh + h] + g_adst[d * Hh + h]);
    atomicMax(&g_emax[d * Hh + h], f2o(v));
}
__global__ __launch_bounds__(256) void init_denom_kernel() {
    int idx = blockIdx.x * 256 + threadIdx.x;
    float self = leaky(g_asrc[idx] + g_adst[idx]);
    g_denom[idx] = expf(self - o2f(g_emax[idx]));
}
__global__ __launch_bounds__(256) void edge_denom_kernel(
    const int* __restrict__ esrc, const int* __restrict__ edst)
{
    int idx = blockIdx.x * 256 + threadIdx.x;
    int e = idx >> 2, h = idx & 3;
    int s = esrc[e], d = edst[e];
    float v = leaky(g_asrc[s * Hh + h] + g_adst[d * Hh + h]);
    atomicAdd(&g_denom[d * Hh + h], expf(v - o2f(g_emax[d * Hh + h])));
}

// ---------------- aggregation (head-mean folded in) ----------------
__global__ __launch_bounds__(256) void self_agg_kernel() {
    int n = blockIdx.x, t = threadIdx.x;
    __shared__ float w[Hh];
    if (t < Hh) {
        float self = leaky(g_asrc[n * Hh + t] + g_adst[n * Hh + t]);
        w[t] = expf(self - o2f(g_emax[n * Hh + t])) / g_denom[n * Hh + t] * (1.0f / Hh);
    }
    __syncthreads();
    const float* xr = g_xh + (size_t)n * HD;
    float acc = 0.f;
    #pragma unroll
    for (int h = 0; h < Hh; h++) acc = fmaf(w[h], xr[h * Cc + t], acc);
    g_agg[(size_t)n * Dm + t] = acc;
}
__global__ __launch_bounds__(256) void edge_agg_kernel(
    const int* __restrict__ esrc, const int* __restrict__ edst)
{
    int e = blockIdx.x, t = threadIdx.x;
    __shared__ float w[Hh];
    __shared__ int sh_s, sh_d;
    if (t == 0) { sh_s = esrc[e]; sh_d = edst[e]; }
    if (t < Hh) {
        int s = esrc[e], d = edst[e];
        float v = leaky(g_asrc[s * Hh + t] + g_adst[d * Hh + t]);
        w[t] = expf(v - o2f(g_emax[d * Hh + t])) / g_denom[d * Hh + t] * (1.0f / Hh);
    }
    __syncthreads();
    const float* xr = g_xh + (size_t)sh_s * HD;
    float acc = 0.f;
    #pragma unroll
    for (int h = 0; h < Hh; h++) acc = fmaf(w[h], xr[h * Cc + t], acc);
    atomicAdd(&g_agg[(size_t)sh_d * Dm + t], acc);
}

// ---------------- launch ----------------
extern "C" void kernel_launch(void* const* d_in, const int* in_sizes, int n_in,
                              void* d_out, int out_size)
{
    const float* inputs   = (const float*)d_in[0];
    const int*   eidx     = (const int*)d_in[1];
    const float* ln_gamma = (const float*)d_in[2];
    const float* ln_beta  = (const float*)d_in[3];
    const float* W1       = (const float*)d_in[4];
    const float* b1       = (const float*)d_in[5];
    const float* W_gat    = (const float*)d_in[6];
    const float* att_src  = (const float*)d_in[7];
    const float* att_dst  = (const float*)d_in[8];
    const float* bias_gat = (const float*)d_in[9];
    const float* W2       = (const float*)d_in[10];
    const float* b2       = (const float*)d_in[11];
    float*       out      = (float*)d_out;

    const int* esrc = eidx;
    const int* edst = eidx + Ee;

    __nv_bfloat16 *xln_hi, *xln_lo, *gnn_hi, *gnn_lo, *agg_hi, *agg_lo;
    __nv_bfloat16 *w1_hi, *w1_lo, *wg_hi, *wg_lo, *w2_hi, *w2_lo;
    float *xh, *agg;
    cudaGetSymbolAddress((void**)&xln_hi, g_xln_hi);
    cudaGetSymbolAddress((void**)&xln_lo, g_xln_lo);
    cudaGetSymbolAddress((void**)&gnn_hi, g_gnn_hi);
    cudaGetSymbolAddress((void**)&gnn_lo, g_gnn_lo);
    cudaGetSymbolAddress((void**)&agg_hi, g_agg_hi);
    cudaGetSymbolAddress((void**)&agg_lo, g_agg_lo);
    cudaGetSymbolAddress((void**)&w1_hi, g_w1_hi);
    cudaGetSymbolAddress((void**)&w1_lo, g_w1_lo);
    cudaGetSymbolAddress((void**)&wg_hi, g_wg_hi);
    cudaGetSymbolAddress((void**)&wg_lo, g_wg_lo);
    cudaGetSymbolAddress((void**)&w2_hi, g_w2_hi);
    cudaGetSymbolAddress((void**)&w2_lo, g_w2_lo);
    cudaGetSymbolAddress((void**)&xh,  g_xh);
    cudaGetSymbolAddress((void**)&agg, g_agg);

    cudaFuncSetAttribute(gemm_mma, cudaFuncAttributeMaxDynamicSharedMemorySize, GEMM_SMEM);

    // weight splits
    split_kernel<<<(Dm * Dm) / 256, 256>>>(W1,    w1_hi, w1_lo, nullptr, 0);
    split_kernel<<<(HD * Dm) / 256, 256>>>(W_gat, wg_hi, wg_lo, nullptr, 0);
    split_kernel<<<(Dm * Dm) / 256, 256>>>(W2,    w2_hi, w2_lo, nullptr, 0);

    // 1) LayerNorm -> xln hi/lo
    ln_kernel<<<Nn_NODES, 256>>>(inputs, ln_gamma, ln_beta);

    // 2) gnn = xln @ W1^T + b1  (bf16 hi/lo out)
    gemm_mma<<<dim3(Dm / 128, Nn_NODES / 128), 256, GEMM_SMEM>>>(
        xln_hi, xln_lo, w1_hi, w1_lo, Dm, b1, nullptr, nullptr, gnn_hi, gnn_lo);

    // 3) xh = gnn @ W_gat^T  (fp32 out)
    gemm_mma<<<dim3(HD / 128, Nn_NODES / 128), 256, GEMM_SMEM>>>(
        gnn_hi, gnn_lo, wg_hi, wg_lo, HD, nullptr, nullptr, xh, nullptr, nullptr);

    // 4) attention dots
    att_dot_kernel<<<Nn_NODES, 128>>>(att_src, att_dst);

    // 5) segment softmax
    init_max_kernel<<<(Nn_NODES * Hh) / 256, 256>>>();
    edge_max_kernel<<<(Ee * Hh) / 256, 256>>>(esrc, edst);
    init_denom_kernel<<<(Nn_NODES * Hh) / 256, 256>>>();
    edge_denom_kernel<<<(Ee * Hh) / 256, 256>>>(esrc, edst);

    // 6) aggregation
    self_agg_kernel<<<Nn_NODES, 256>>>();
    edge_agg_kernel<<<Ee, 256>>>(esrc, edst);

    // 7) (agg + bias_gat) -> hi/lo ; out = agg' @ W2^T + b2 + inputs
    split_kernel<<<(Nn_NODES * Dm) / 256, 256>>>(agg, agg_hi, agg_lo, bias_gat, Dm - 1);
    gemm_mma<<<dim3(Dm / 128, Nn_NODES / 128), 256, GEMM_SMEM>>>(
        agg_hi, agg_lo, w2_hi, w2_lo, Dm, b2, inputs, out, nullptr, nullptr);
}

// round 5
// speedup vs baseline: 2.1331x; 1.1772x over previous
#include <cuda_runtime.h>
#include <cuda_bf16.h>
#include <cstdint>

// ---------------- problem constants ----------------
#define Nn_NODES 16384      // B*L
#define Dm 256              // d_model
#define Hh 4                // heads
#define Cc 256              // per-head channels
#define HD (Hh*Cc)          // 1024
#define Ee 65536            // edges
#define NEG_SLOPE 0.2f
#define LN_EPS 1e-6f

// ---------------- device scratch ----------------
__device__ __nv_bfloat16 g_xln_hi[Nn_NODES * Dm];
__device__ __nv_bfloat16 g_xln_lo[Nn_NODES * Dm];
__device__ __nv_bfloat16 g_gnn_hi[Nn_NODES * Dm];
__device__ __nv_bfloat16 g_gnn_lo[Nn_NODES * Dm];
__device__ __nv_bfloat16 g_agg_hi[Nn_NODES * Dm];
__device__ __nv_bfloat16 g_agg_lo[Nn_NODES * Dm];
__device__ __nv_bfloat16 g_w1_hi[Dm * Dm],  g_w1_lo[Dm * Dm];
__device__ __nv_bfloat16 g_wg_hi[HD * Dm],  g_wg_lo[HD * Dm];
__device__ __nv_bfloat16 g_w2_hi[Dm * Dm],  g_w2_lo[Dm * Dm];
__device__ float    g_xh   [Nn_NODES * HD];
__device__ float    g_asrc [Nn_NODES * Hh];
__device__ float    g_adst [Nn_NODES * Hh];
// CSR structures
__device__ int g_deg   [Nn_NODES];
__device__ int g_offs  [Nn_NODES];
__device__ int g_cursor[Nn_NODES];
__device__ int g_bsum  [64];
__device__ int g_csr_src[Ee];

// ---------------- helpers ----------------
__device__ __forceinline__ float leaky(float x) { return x > 0.0f ? x : NEG_SLOPE * x; }
__device__ __forceinline__ unsigned f2o(float f) {
    unsigned u = __float_as_uint(f);
    return (u & 0x80000000u) ? ~u : (u | 0x80000000u);
}
__device__ __forceinline__ float o2f(unsigned u) {
    return (u & 0x80000000u) ? __uint_as_float(u & 0x7FFFFFFFu) : __uint_as_float(~u);
}
__device__ __forceinline__ float warp_sum(float v) {
    #pragma unroll
    for (int o = 16; o > 0; o >>= 1) v += __shfl_xor_sync(0xFFFFFFFFu, v, o);
    return v;
}
__device__ __forceinline__ void split2(float v, __nv_bfloat16& h, __nv_bfloat16& l) {
    h = __float2bfloat16(v);
    l = __float2bfloat16(v - __bfloat162float(h));
}
__device__ __forceinline__ uint32_t smem_to_u32(const void* p) {
    uint32_t a;
    asm("{ .reg .u64 t; cvta.to.shared.u64 t, %1; cvt.u32.u64 %0, t; }"
        : "=r"(a) : "l"(p));
    return a;
}

// ---------------- mma / ldmatrix / cp.async PTX (sm_80-compatible) --------
#define LDM4(r, addr) \
    asm volatile("ldmatrix.sync.aligned.m8n8.x4.shared.b16 {%0,%1,%2,%3}, [%4];" \
        : "=r"((r)[0]), "=r"((r)[1]), "=r"((r)[2]), "=r"((r)[3]) : "r"(addr))

#define MMA_BF16(c, a, b0, b1) \
    asm volatile("mma.sync.aligned.m16n8k16.row.col.f32.bf16.bf16.f32 " \
        "{%0,%1,%2,%3}, {%4,%5,%6,%7}, {%8,%9}, {%0,%1,%2,%3};" \
        : "+f"((c)[0]), "+f"((c)[1]), "+f"((c)[2]), "+f"((c)[3]) \
        : "r"((a)[0]), "r"((a)[1]), "r"((a)[2]), "r"((a)[3]), "r"(b0), "r"(b1))

#define CP_ASYNC16(dst, src) \
    asm volatile("cp.async.cg.shared.global [%0], [%1], 16;" \
        :: "r"(dst), "l"(src) : "memory")
#define CP_COMMIT() asm volatile("cp.async.commit_group;" ::: "memory")
#define CP_WAIT1()  asm volatile("cp.async.wait_group 1;" ::: "memory")
#define CP_WAIT0()  asm volatile("cp.async.wait_group 0;" ::: "memory")

// ---------------- split kernel: fp32 -> bf16 hi/lo ----------------
__global__ __launch_bounds__(256) void split_kernel(
    const float* __restrict__ src, __nv_bfloat16* __restrict__ hi,
    __nv_bfloat16* __restrict__ lo)
{
    int i = blockIdx.x * 256 + threadIdx.x;
    split2(src[i], hi[i], lo[i]);
}

// ---------------- LayerNorm: warp per row, float4 ----------------
__global__ __launch_bounds__(256) void ln_kernel(
    const float* __restrict__ x, const float* __restrict__ gamma,
    const float* __restrict__ beta)
{
    int row  = blockIdx.x * 8 + (threadIdx.x >> 5);
    int lane = threadIdx.x & 31;
    const float* xr = x + (size_t)row * Dm;
    float4 v0 = *(const float4*)(xr + lane * 4);
    float4 v1 = *(const float4*)(xr + 128 + lane * 4);
    float s  = v0.x + v0.y + v0.z + v0.w + v1.x + v1.y + v1.z + v1.w;
    float s2 = v0.x*v0.x + v0.y*v0.y + v0.z*v0.z + v0.w*v0.w
             + v1.x*v1.x + v1.y*v1.y + v1.z*v1.z + v1.w*v1.w;
    s = warp_sum(s);
    s2 = warp_sum(s2);
    float mu   = s * (1.0f / Dm);
    float var  = s2 * (1.0f / Dm) - mu * mu;
    float rstd = rsqrtf(var + LN_EPS);

    float o[8];
    float4 gm0 = *(const float4*)(gamma + lane * 4);
    float4 gm1 = *(const float4*)(gamma + 128 + lane * 4);
    float4 bt0 = *(const float4*)(beta + lane * 4);
    float4 bt1 = *(const float4*)(beta + 128 + lane * 4);
    o[0] = (v0.x - mu) * rstd * gm0.x + bt0.x;
    o[1] = (v0.y - mu) * rstd * gm0.y + bt0.y;
    o[2] = (v0.z - mu) * rstd * gm0.z + bt0.z;
    o[3] = (v0.w - mu) * rstd * gm0.w + bt0.w;
    o[4] = (v1.x - mu) * rstd * gm1.x + bt1.x;
    o[5] = (v1.y - mu) * rstd * gm1.y + bt1.y;
    o[6] = (v1.z - mu) * rstd * gm1.z + bt1.z;
    o[7] = (v1.w - mu) * rstd * gm1.w + bt1.w;
    #pragma unroll
    for (int i = 0; i < 8; i++) {
        size_t idx = (size_t)row * Dm + (i < 4 ? lane * 4 + i : 128 + lane * 4 + i - 4);
        split2(o[i], g_xln_hi[idx], g_xln_lo[idx]);
    }
}

// ---------------- bf16x3 HMMA GEMM (3-stage cp.async, pass-major MMA) -----
#define ST_STRIDE 65536
#define O_AH 0
#define O_AL 16384
#define O_BH 32768
#define O_BL 49152
#define GEMM_SMEM (3 * ST_STRIDE)

__global__ __launch_bounds__(256) void gemm_mma(
    const __nv_bfloat16* __restrict__ Ahi, const __nv_bfloat16* __restrict__ Alo,
    const __nv_bfloat16* __restrict__ Bhi, const __nv_bfloat16* __restrict__ Blo,
    int Ncols, const float* __restrict__ c_bias, const float* __restrict__ resid,
    float* __restrict__ Cf32, __nv_bfloat16* __restrict__ Chi,
    __nv_bfloat16* __restrict__ Clo)
{
    extern __shared__ char smem[];
    uint32_t sb = smem_to_u32(smem);
    const int tid = threadIdx.x, lane = tid & 31, wid = tid >> 5;
    const int warp_m0 = (wid >> 2) * 64;
    const int warp_n0 = (wid & 3) * 32;
    const size_t m0 = (size_t)blockIdx.y * 128;
    const size_t n0 = (size_t)blockIdx.x * 128;

    float acc[4][4][4];
    #pragma unroll
    for (int i = 0; i < 4; i++)
        #pragma unroll
        for (int j = 0; j < 4; j++)
            #pragma unroll
            for (int k = 0; k < 4; k++) acc[i][j][k] = 0.f;

    const int arow = lane & 15;
    const int akb  = (lane >> 4) << 4;
    const int brl  = ((lane >> 4) << 3) | (lane & 7);
    const int bkb  = ((lane >> 3) & 1) << 4;
    const uint32_t aswz = (uint32_t)(arow & 7) << 4;
    const uint32_t bswz = (uint32_t)(lane & 7) << 4;

    auto issue = [&](int stage, int kc0) {
        uint32_t s0 = sb + stage * ST_STRIDE;
        #pragma unroll
        for (int it = 0; it < 4; ++it) {
            int idx = tid + it * 256;
            int row = idx >> 3, c16 = idx & 7;
            uint32_t off = (uint32_t)row * 128 + c16 * 16;
            off ^= ((uint32_t)(row & 7)) << 4;           // SW128
            size_t gA = (m0 + row) * 256 + kc0 + c16 * 8;
            size_t gB = (n0 + row) * 256 + kc0 + c16 * 8;
            CP_ASYNC16(s0 + O_AH + off, Ahi + gA);
            CP_ASYNC16(s0 + O_AL + off, Alo + gA);
            CP_ASYNC16(s0 + O_BH + off, Bhi + gB);
            CP_ASYNC16(s0 + O_BL + off, Blo + gB);
        }
    };

    issue(0, 0);   CP_COMMIT();
    issue(1, 64);  CP_COMMIT();

    for (int kc = 0; kc < 4; ++kc) {
        if (kc < 3) { CP_WAIT1(); } else { CP_WAIT0(); }
        __syncthreads();
        if (kc + 2 < 4) { issue((kc + 2) % 3, (kc + 2) * 64); CP_COMMIT(); }

        uint32_t st = sb + (kc % 3) * ST_STRIDE;
        #pragma unroll
        for (int k16 = 0; k16 < 4; ++k16) {
            int kbyte = k16 * 32;
            uint32_t ah[4][4], al[4][4], bh[2][4], bl[2][4];
            #pragma unroll
            for (int mt = 0; mt < 4; ++mt) {
                uint32_t ad = st + O_AH +
                    (uint32_t)(warp_m0 + mt * 16 + arow) * 128 + kbyte + akb;
                LDM4(ah[mt], ad ^ aswz);
                LDM4(al[mt], (ad + (O_AL - O_AH)) ^ aswz);
            }
            #pragma unroll
            for (int g2 = 0; g2 < 2; ++g2) {
                uint32_t bd = st + O_BH +
                    (uint32_t)(warp_n0 + g2 * 16 + brl) * 128 + kbyte + bkb;
                LDM4(bh[g2], bd ^ bswz);
                LDM4(bl[g2], (bd + (O_BL - O_BH)) ^ bswz);
            }
            // pass-major ordering: 16 independent MMAs per pass
            #pragma unroll
            for (int mt = 0; mt < 4; ++mt)
                #pragma unroll
                for (int nt = 0; nt < 4; ++nt) {
                    int g2 = nt >> 1, p = (nt & 1) << 1;
                    MMA_BF16(acc[mt][nt], ah[mt], bh[g2][p], bh[g2][p + 1]);
                }
            #pragma unroll
            for (int mt = 0; mt < 4; ++mt)
                #pragma unroll
                for (int nt = 0; nt < 4; ++nt) {
                    int g2 = nt >> 1, p = (nt & 1) << 1;
                    MMA_BF16(acc[mt][nt], ah[mt], bl[g2][p], bl[g2][p + 1]);
                }
            #pragma unroll
            for (int mt = 0; mt < 4; ++mt)
                #pragma unroll
                for (int nt = 0; nt < 4; ++nt) {
                    int g2 = nt >> 1, p = (nt & 1) << 1;
                    MMA_BF16(acc[mt][nt], al[mt], bh[g2][p], bh[g2][p + 1]);
                }
        }
        __syncthreads();
    }

    // epilogue
    const int g = lane >> 2, tq = lane & 3;
    #pragma unroll
    for (int mt = 0; mt < 4; ++mt) {
        #pragma unroll
        for (int nt = 0; nt < 4; ++nt) {
            size_t r = m0 + warp_m0 + mt * 16 + g;
            size_t c = n0 + warp_n0 + nt * 8 + tq * 2;
            float v00 = acc[mt][nt][0], v01 = acc[mt][nt][1];
            float v10 = acc[mt][nt][2], v11 = acc[mt][nt][3];
            if (c_bias) {
                float cb0 = c_bias[c], cb1 = c_bias[c + 1];
                v00 += cb0; v01 += cb1; v10 += cb0; v11 += cb1;
            }
            size_t o0 = r * (size_t)Ncols + c;
            size_t o1 = (r + 8) * (size_t)Ncols + c;
            if (resid) {
                v00 += resid[o0]; v01 += resid[o0 + 1];
                v10 += resid[o1]; v11 += resid[o1 + 1];
            }
            if (Cf32) {
                *(float2*)(Cf32 + o0) = make_float2(v00, v01);
                *(float2*)(Cf32 + o1) = make_float2(v10, v11);
            }
            if (Chi) {
                split2(v00, Chi[o0], Clo[o0]);
                split2(v01, Chi[o0 + 1], Clo[o0 + 1]);
                split2(v10, Chi[o1], Clo[o1]);
                split2(v11, Chi[o1 + 1], Clo[o1 + 1]);
            }
        }
    }
}

// ---------------- attention dots ----------------
__global__ __launch_bounds__(128) void att_dot_kernel(
    const float* __restrict__ att_src, const float* __restrict__ att_dst)
{
    int n = blockIdx.x;
    int h = threadIdx.x >> 5;
    int lane = threadIdx.x & 31;
    const float* xr = g_xh + (size_t)n * HD + h * Cc;
    float s = 0.f, d = 0.f;
    #pragma unroll
    for (int i = 0; i < 8; i++) {
        int c = lane + 32 * i;
        float x = xr[c];
        s = fmaf(x, att_src[h * Cc + c], s);
        d = fmaf(x, att_dst[h * Cc + c], d);
    }
    s = warp_sum(s);
    d = warp_sum(d);
    if (lane == 0) { g_asrc[n * Hh + h] = s; g_adst[n * Hh + h] = d; }
}

// ---------------- CSR build ----------------
__global__ __launch_bounds__(256) void hist_kernel(const int* __restrict__ edst) {
    int e = blockIdx.x * 256 + threadIdx.x;
    atomicAdd(&g_deg[edst[e]], 1);
}
__global__ __launch_bounds__(256) void scanA_kernel() {
    __shared__ int sh[256];
    int i = blockIdx.x * 256 + threadIdx.x;
    int v = g_deg[i];
    sh[threadIdx.x] = v;
    __syncthreads();
    for (int off = 1; off < 256; off <<= 1) {
        int add = (threadIdx.x >= off) ? sh[threadIdx.x - off] : 0;
        __syncthreads();
        sh[threadIdx.x] += add;
        __syncthreads();
    }
    g_offs[i] = sh[threadIdx.x] - v;
    if (threadIdx.x == 255) g_bsum[blockIdx.x] = sh[255];
}
__global__ void scanB_kernel() {
    int run = 0;
    for (int i = 0; i < 64; i++) { int v = g_bsum[i]; g_bsum[i] = run; run += v; }
}
__global__ __launch_bounds__(256) void scanC_kernel() {
    int i = blockIdx.x * 256 + threadIdx.x;
    g_offs[i] += g_bsum[blockIdx.x];
}
__global__ __launch_bounds__(256) void scatter_kernel(
    const int* __restrict__ esrc, const int* __restrict__ edst)
{
    int e = blockIdx.x * 256 + threadIdx.x;
    int d = edst[e];
    int pos = g_offs[d] + atomicAdd(&g_cursor[d], 1);
    g_csr_src[pos] = esrc[e];
}

// ---------------- fused node softmax + aggregation (no global atomics) ----
#define MAXCH 64
__global__ __launch_bounds__(256) void node_agg_kernel(
    const float* __restrict__ bias_gat)
{
    int n = blockIdx.x, t = threadIdx.x;
    int start = g_offs[n], dcount = g_deg[n];

    __shared__ unsigned s_max[Hh];
    __shared__ float s_den[Hh];
    __shared__ float s_adst[Hh], s_self[Hh], s_wself[Hh];
    __shared__ float s_w[MAXCH][Hh];
    __shared__ int s_src[MAXCH];

    if (t < Hh) {
        float as = g_asrc[n * Hh + t], ad = g_adst[n * Hh + t];
        s_adst[t] = ad;
        float self = leaky(as + ad);
        s_self[t] = self;
        s_max[t] = f2o(self);
    }
    __syncthreads();

    int et = t >> 2, h = t & 3;
    // pass 1: max
    for (int base = 0; base < dcount; base += MAXCH) {
        int e = base + et;
        if (e < dcount) {
            int s = g_csr_src[start + e];
            float logit = leaky(g_asrc[s * Hh + h] + s_adst[h]);
            atomicMax(&s_max[h], f2o(logit));
        }
    }
    __syncthreads();
    if (t < Hh) s_den[t] = expf(s_self[t] - o2f(s_max[t]));
    __syncthreads();
    // pass 2: denom
    for (int base = 0; base < dcount; base += MAXCH) {
        int e = base + et;
        if (e < dcount) {
            int s = g_csr_src[start + e];
            float logit = leaky(g_asrc[s * Hh + h] + s_adst[h]);
            atomicAdd(&s_den[h], expf(logit - o2f(s_max[h])));
        }
    }
    __syncthreads();
    if (t < Hh)
        s_wself[t] = expf(s_self[t] - o2f(s_max[t])) / s_den[t] * (1.0f / Hh);
    __syncthreads();

    // pass 3: aggregate (self + edges)
    const float* xn = g_xh + (size_t)n * HD;
    float acc = 0.f;
    #pragma unroll
    for (int hh = 0; hh < Hh; hh++) acc = fmaf(s_wself[hh], xn[hh * Cc + t], acc);

    for (int base = 0; base < dcount; base += MAXCH) {
        int cnt = min(MAXCH, dcount - base);
        int e = base + et;
        if (e < dcount) {
            int s = g_csr_src[start + e];
            float logit = leaky(g_asrc[s * Hh + h] + s_adst[h]);
            s_w[et][h] = expf(logit - o2f(s_max[h])) / s_den[h] * (1.0f / Hh);
            if (h == 0) s_src[et] = s;
        }
        __syncthreads();
        for (int e2 = 0; e2 < cnt; e2++) {
            const float* xr = g_xh + (size_t)s_src[e2] * HD;
            #pragma unroll
            for (int hh = 0; hh < Hh; hh++)
                acc = fmaf(s_w[e2][hh], xr[hh * Cc + t], acc);
        }
        __syncthreads();
    }

    float v = acc + bias_gat[t];
    split2(v, g_agg_hi[(size_t)n * Dm + t], g_agg_lo[(size_t)n * Dm + t]);
}

// ---------------- launch ----------------
extern "C" void kernel_launch(void* const* d_in, const int* in_sizes, int n_in,
                              void* d_out, int out_size)
{
    const float* inputs   = (const float*)d_in[0];
    const int*   eidx     = (const int*)d_in[1];
    const float* ln_gamma = (const float*)d_in[2];
    const float* ln_beta  = (const float*)d_in[3];
    const float* W1       = (const float*)d_in[4];
    const float* b1       = (const float*)d_in[5];
    const float* W_gat    = (const float*)d_in[6];
    const float* att_src  = (const float*)d_in[7];
    const float* att_dst  = (const float*)d_in[8];
    const float* bias_gat = (const float*)d_in[9];
    const float* W2       = (const float*)d_in[10];
    const float* b2       = (const float*)d_in[11];
    float*       out      = (float*)d_out;

    const int* esrc = eidx;
    const int* edst = eidx + Ee;

    __nv_bfloat16 *xln_hi, *xln_lo, *gnn_hi, *gnn_lo, *agg_hi, *agg_lo;
    __nv_bfloat16 *w1_hi, *w1_lo, *wg_hi, *wg_lo, *w2_hi, *w2_lo;
    float *xh;
    int *degp, *curp;
    cudaGetSymbolAddress((void**)&xln_hi, g_xln_hi);
    cudaGetSymbolAddress((void**)&xln_lo, g_xln_lo);
    cudaGetSymbolAddress((void**)&gnn_hi, g_gnn_hi);
    cudaGetSymbolAddress((void**)&gnn_lo, g_gnn_lo);
    cudaGetSymbolAddress((void**)&agg_hi, g_agg_hi);
    cudaGetSymbolAddress((void**)&agg_lo, g_agg_lo);
    cudaGetSymbolAddress((void**)&w1_hi, g_w1_hi);
    cudaGetSymbolAddress((void**)&w1_lo, g_w1_lo);
    cudaGetSymbolAddress((void**)&wg_hi, g_wg_hi);
    cudaGetSymbolAddress((void**)&wg_lo, g_wg_lo);
    cudaGetSymbolAddress((void**)&w2_hi, g_w2_hi);
    cudaGetSymbolAddress((void**)&w2_lo, g_w2_lo);
    cudaGetSymbolAddress((void**)&xh,  g_xh);
    cudaGetSymbolAddress((void**)&degp, g_deg);
    cudaGetSymbolAddress((void**)&curp, g_cursor);

    cudaFuncSetAttribute(gemm_mma, cudaFuncAttributeMaxDynamicSharedMemorySize, GEMM_SMEM);

    // CSR build (independent of GEMMs; needs only the edge list)
    cudaMemsetAsync(degp, 0, Nn_NODES * sizeof(int));
    cudaMemsetAsync(curp, 0, Nn_NODES * sizeof(int));
    hist_kernel<<<Ee / 256, 256>>>(edst);
    scanA_kernel<<<Nn_NODES / 256, 256>>>();
    scanB_kernel<<<1, 1>>>();
    scanC_kernel<<<Nn_NODES / 256, 256>>>();
    scatter_kernel<<<Ee / 256, 256>>>(esrc, edst);

    // weight splits
    split_kernel<<<(Dm * Dm) / 256, 256>>>(W1,    w1_hi, w1_lo);
    split_kernel<<<(HD * Dm) / 256, 256>>>(W_gat, wg_hi, wg_lo);
    split_kernel<<<(Dm * Dm) / 256, 256>>>(W2,    w2_hi, w2_lo);

    // 1) LayerNorm -> xln hi/lo
    ln_kernel<<<Nn_NODES / 8, 256>>>(inputs, ln_gamma, ln_beta);

    // 2) gnn = xln @ W1^T + b1  (bf16 hi/lo out)
    gemm_mma<<<dim3(Dm / 128, Nn_NODES / 128), 256, GEMM_SMEM>>>(
        xln_hi, xln_lo, w1_hi, w1_lo, Dm, b1, nullptr, nullptr, gnn_hi, gnn_lo);

    // 3) xh = gnn @ W_gat^T  (fp32 out)
    gemm_mma<<<dim3(HD / 128, Nn_NODES / 128), 256, GEMM_SMEM>>>(
        gnn_hi, gnn_lo, wg_hi, wg_lo, HD, nullptr, nullptr, xh, nullptr, nullptr);

    // 4) attention dots
    att_dot_kernel<<<Nn_NODES, 128>>>(att_src, att_dst);

    // 5+6) fused segment softmax + aggregation (CSR, no global atomics)
    node_agg_kernel<<<Nn_NODES, 256>>>(bias_gat);

    // 7) out = (agg + bias_gat) @ W2^T + b2 + inputs
    gemm_mma<<<dim3(Dm / 128, Nn_NODES / 128), 256, GEMM_SMEM>>>(
        agg_hi, agg_lo, w2_hi, w2_lo, Dm, b2, inputs, out, nullptr, nullptr);
}

// round 6
// speedup vs baseline: 2.1356x; 1.0012x over previous
#include <cuda_runtime.h>
#include <cuda_bf16.h>
#include <cstdint>

// ---------------- problem constants ----------------
#define Nn_NODES 16384      // B*L
#define Dm 256              // d_model
#define Hh 4                // heads
#define Cc 256              // per-head channels
#define HD (Hh*Cc)          // 1024
#define Ee 65536            // edges
#define NEG_SLOPE 0.2f
#define LN_EPS 1e-6f

// ---------------- device scratch ----------------
__device__ __nv_bfloat16 g_xln_hi[Nn_NODES * Dm];
__device__ __nv_bfloat16 g_xln_lo[Nn_NODES * Dm];
__device__ __nv_bfloat16 g_gnn_hi[Nn_NODES * Dm];
__device__ __nv_bfloat16 g_gnn_lo[Nn_NODES * Dm];
__device__ __nv_bfloat16 g_agg_hi[Nn_NODES * Dm];
__device__ __nv_bfloat16 g_agg_lo[Nn_NODES * Dm];
__device__ __nv_bfloat16 g_w1_hi[Dm * Dm],  g_w1_lo[Dm * Dm];
__device__ __nv_bfloat16 g_wg_hi[HD * Dm],  g_wg_lo[HD * Dm];
__device__ __nv_bfloat16 g_w2_hi[Dm * Dm],  g_w2_lo[Dm * Dm];
__device__ float    g_xh   [Nn_NODES * HD];
__device__ float    g_asrc [Nn_NODES * Hh];
__device__ float    g_adst [Nn_NODES * Hh];
// CSR structures
__device__ int g_deg   [Nn_NODES];
__device__ int g_offs  [Nn_NODES];
__device__ int g_cursor[Nn_NODES];
__device__ int g_csr_src[Ee];

// ---------------- helpers ----------------
__device__ __forceinline__ float leaky(float x) { return x > 0.0f ? x : NEG_SLOPE * x; }
__device__ __forceinline__ unsigned f2o(float f) {
    unsigned u = __float_as_uint(f);
    return (u & 0x80000000u) ? ~u : (u | 0x80000000u);
}
__device__ __forceinline__ float o2f(unsigned u) {
    return (u & 0x80000000u) ? __uint_as_float(u & 0x7FFFFFFFu) : __uint_as_float(~u);
}
__device__ __forceinline__ float warp_sum(float v) {
    #pragma unroll
    for (int o = 16; o > 0; o >>= 1) v += __shfl_xor_sync(0xFFFFFFFFu, v, o);
    return v;
}
__device__ __forceinline__ void split2(float v, __nv_bfloat16& h, __nv_bfloat16& l) {
    h = __float2bfloat16(v);
    l = __float2bfloat16(v - __bfloat162float(h));
}
__device__ __forceinline__ uint32_t smem_to_u32(const void* p) {
    uint32_t a;
    asm("{ .reg .u64 t; cvta.to.shared.u64 t, %1; cvt.u32.u64 %0, t; }"
        : "=r"(a) : "l"(p));
    return a;
}

// ---------------- mma / ldmatrix / cp.async PTX (sm_80-compatible) --------
#define LDM4(r, addr) \
    asm volatile("ldmatrix.sync.aligned.m8n8.x4.shared.b16 {%0,%1,%2,%3}, [%4];" \
        : "=r"((r)[0]), "=r"((r)[1]), "=r"((r)[2]), "=r"((r)[3]) : "r"(addr))

#define MMA_BF16(c, a, b0, b1) \
    asm volatile("mma.sync.aligned.m16n8k16.row.col.f32.bf16.bf16.f32 " \
        "{%0,%1,%2,%3}, {%4,%5,%6,%7}, {%8,%9}, {%0,%1,%2,%3};" \
        : "+f"((c)[0]), "+f"((c)[1]), "+f"((c)[2]), "+f"((c)[3]) \
        : "r"((a)[0]), "r"((a)[1]), "r"((a)[2]), "r"((a)[3]), "r"(b0), "r"(b1))

#define CP_ASYNC16(dst, src) \
    asm volatile("cp.async.cg.shared.global [%0], [%1], 16;" \
        :: "r"(dst), "l"(src) : "memory")
#define CP_COMMIT() asm volatile("cp.async.commit_group;" ::: "memory")
#define CP_WAIT1()  asm volatile("cp.async.wait_group 1;" ::: "memory")
#define CP_WAIT0()  asm volatile("cp.async.wait_group 0;" ::: "memory")

// ---------------- zero kernel (deg, cursor, asrc, adst) ----------------
__global__ __launch_bounds__(256) void zero_kernel() {
    int i = blockIdx.x * 256 + threadIdx.x;     // grid covers 65536
    if (i < Nn_NODES) { g_deg[i] = 0; g_cursor[i] = 0; }
    g_asrc[i] = 0.f;
    g_adst[i] = 0.f;
}

// ---------------- fused weight split ----------------
__global__ __launch_bounds__(256) void splitW_kernel(
    const float* __restrict__ W1, const float* __restrict__ Wg,
    const float* __restrict__ W2)
{
    int i = blockIdx.x * 256 + threadIdx.x;     // grid covers HD*Dm = 262144
    if (i < Dm * Dm) {
        split2(W1[i], g_w1_hi[i], g_w1_lo[i]);
        split2(W2[i], g_w2_hi[i], g_w2_lo[i]);
    }
    split2(Wg[i], g_wg_hi[i], g_wg_lo[i]);
}

// ---------------- LayerNorm: warp per row, float4 ----------------
__global__ __launch_bounds__(256) void ln_kernel(
    const float* __restrict__ x, const float* __restrict__ gamma,
    const float* __restrict__ beta)
{
    int row  = blockIdx.x * 8 + (threadIdx.x >> 5);
    int lane = threadIdx.x & 31;
    const float* xr = x + (size_t)row * Dm;
    float4 v0 = *(const float4*)(xr + lane * 4);
    float4 v1 = *(const float4*)(xr + 128 + lane * 4);
    float s  = v0.x + v0.y + v0.z + v0.w + v1.x + v1.y + v1.z + v1.w;
    float s2 = v0.x*v0.x + v0.y*v0.y + v0.z*v0.z + v0.w*v0.w
             + v1.x*v1.x + v1.y*v1.y + v1.z*v1.z + v1.w*v1.w;
    s = warp_sum(s);
    s2 = warp_sum(s2);
    float mu   = s * (1.0f / Dm);
    float var  = s2 * (1.0f / Dm) - mu * mu;
    float rstd = rsqrtf(var + LN_EPS);

    float o[8];
    float4 gm0 = *(const float4*)(gamma + lane * 4);
    float4 gm1 = *(const float4*)(gamma + 128 + lane * 4);
    float4 bt0 = *(const float4*)(beta + lane * 4);
    float4 bt1 = *(const float4*)(beta + 128 + lane * 4);
    o[0] = (v0.x - mu) * rstd * gm0.x + bt0.x;
    o[1] = (v0.y - mu) * rstd * gm0.y + bt0.y;
    o[2] = (v0.z - mu) * rstd * gm0.z + bt0.z;
    o[3] = (v0.w - mu) * rstd * gm0.w + bt0.w;
    o[4] = (v1.x - mu) * rstd * gm1.x + bt1.x;
    o[5] = (v1.y - mu) * rstd * gm1.y + bt1.y;
    o[6] = (v1.z - mu) * rstd * gm1.z + bt1.z;
    o[7] = (v1.w - mu) * rstd * gm1.w + bt1.w;
    #pragma unroll
    for (int i = 0; i < 8; i++) {
        size_t idx = (size_t)row * Dm + (i < 4 ? lane * 4 + i : 128 + lane * 4 + i - 4);
        split2(o[i], g_xln_hi[idx], g_xln_lo[idx]);
    }
}

// ---------------- bf16x3 HMMA GEMM (3-stage cp.async, pass-major MMA) -----
// Optional fused attention-dot epilogue (att_s/att_d non-null): partial dots
// of the output tile against per-head att vectors, atomicAdd into g_asrc/adst.
#define ST_STRIDE 65536
#define O_AH 0
#define O_AL 16384
#define O_BH 32768
#define O_BL 49152
#define GEMM_SMEM (3 * ST_STRIDE)

__global__ __launch_bounds__(256) void gemm_mma(
    const __nv_bfloat16* __restrict__ Ahi, const __nv_bfloat16* __restrict__ Alo,
    const __nv_bfloat16* __restrict__ Bhi, const __nv_bfloat16* __restrict__ Blo,
    int Ncols, const float* __restrict__ c_bias, const float* __restrict__ resid,
    float* __restrict__ Cf32, __nv_bfloat16* __restrict__ Chi,
    __nv_bfloat16* __restrict__ Clo,
    const float* __restrict__ att_s, const float* __restrict__ att_d)
{
    extern __shared__ char smem[];
    uint32_t sb = smem_to_u32(smem);
    const int tid = threadIdx.x, lane = tid & 31, wid = tid >> 5;
    const int warp_m0 = (wid >> 2) * 64;
    const int warp_n0 = (wid & 3) * 32;
    const size_t m0 = (size_t)blockIdx.y * 128;
    const size_t n0 = (size_t)blockIdx.x * 128;

    float acc[4][4][4];
    #pragma unroll
    for (int i = 0; i < 4; i++)
        #pragma unroll
        for (int j = 0; j < 4; j++)
            #pragma unroll
            for (int k = 0; k < 4; k++) acc[i][j][k] = 0.f;

    const int arow = lane & 15;
    const int akb  = (lane >> 4) << 4;
    const int brl  = ((lane >> 4) << 3) | (lane & 7);
    const int bkb  = ((lane >> 3) & 1) << 4;
    const uint32_t aswz = (uint32_t)(arow & 7) << 4;
    const uint32_t bswz = (uint32_t)(lane & 7) << 4;

    auto issue = [&](int stage, int kc0) {
        uint32_t s0 = sb + stage * ST_STRIDE;
        #pragma unroll
        for (int it = 0; it < 4; ++it) {
            int idx = tid + it * 256;
            int row = idx >> 3, c16 = idx & 7;
            uint32_t off = (uint32_t)row * 128 + c16 * 16;
            off ^= ((uint32_t)(row & 7)) << 4;           // SW128
            size_t gA = (m0 + row) * 256 + kc0 + c16 * 8;
            size_t gB = (n0 + row) * 256 + kc0 + c16 * 8;
            CP_ASYNC16(s0 + O_AH + off, Ahi + gA);
            CP_ASYNC16(s0 + O_AL + off, Alo + gA);
            CP_ASYNC16(s0 + O_BH + off, Bhi + gB);
            CP_ASYNC16(s0 + O_BL + off, Blo + gB);
        }
    };

    issue(0, 0);   CP_COMMIT();
    issue(1, 64);  CP_COMMIT();

    for (int kc = 0; kc < 4; ++kc) {
        if (kc < 3) { CP_WAIT1(); } else { CP_WAIT0(); }
        __syncthreads();
        if (kc + 2 < 4) { issue((kc + 2) % 3, (kc + 2) * 64); CP_COMMIT(); }

        uint32_t st = sb + (kc % 3) * ST_STRIDE;
        #pragma unroll
        for (int k16 = 0; k16 < 4; ++k16) {
            int kbyte = k16 * 32;
            uint32_t ah[4][4], al[4][4], bh[2][4], bl[2][4];
            #pragma unroll
            for (int mt = 0; mt < 4; ++mt) {
                uint32_t ad = st + O_AH +
                    (uint32_t)(warp_m0 + mt * 16 + arow) * 128 + kbyte + akb;
                LDM4(ah[mt], ad ^ aswz);
                LDM4(al[mt], (ad + (O_AL - O_AH)) ^ aswz);
            }
            #pragma unroll
            for (int g2 = 0; g2 < 2; ++g2) {
                uint32_t bd = st + O_BH +
                    (uint32_t)(warp_n0 + g2 * 16 + brl) * 128 + kbyte + bkb;
                LDM4(bh[g2], bd ^ bswz);
                LDM4(bl[g2], (bd + (O_BL - O_BH)) ^ bswz);
            }
            // pass-major: 16 independent MMAs per pass
            #pragma unroll
            for (int mt = 0; mt < 4; ++mt)
                #pragma unroll
                for (int nt = 0; nt < 4; ++nt) {
                    int g2 = nt >> 1, p = (nt & 1) << 1;
                    MMA_BF16(acc[mt][nt], ah[mt], bh[g2][p], bh[g2][p + 1]);
                }
            #pragma unroll
            for (int mt = 0; mt < 4; ++mt)
                #pragma unroll
                for (int nt = 0; nt < 4; ++nt) {
                    int g2 = nt >> 1, p = (nt & 1) << 1;
                    MMA_BF16(acc[mt][nt], ah[mt], bl[g2][p], bl[g2][p + 1]);
                }
            #pragma unroll
            for (int mt = 0; mt < 4; ++mt)
                #pragma unroll
                for (int nt = 0; nt < 4; ++nt) {
                    int g2 = nt >> 1, p = (nt & 1) << 1;
                    MMA_BF16(acc[mt][nt], al[mt], bh[g2][p], bh[g2][p + 1]);
                }
        }
        __syncthreads();
    }

    // ---- epilogue ----
    const int g = lane >> 2, tq = lane & 3;

    // fused attention-dot coefficients (one head per 256-col block)
    const int h_att = (int)(n0 >> 8);
    float as0[4], as1[4], ad0[4], ad1[4];
    float ps[4][2], pd[4][2];
    if (att_s) {
        int cih0 = (int)(n0 & 255) + warp_n0 + tq * 2;
        #pragma unroll
        for (int nt = 0; nt < 4; ++nt) {
            int cih = cih0 + nt * 8;
            as0[nt] = att_s[h_att * Cc + cih];
            as1[nt] = att_s[h_att * Cc + cih + 1];
            ad0[nt] = att_d[h_att * Cc + cih];
            ad1[nt] = att_d[h_att * Cc + cih + 1];
        }
        #pragma unroll
        for (int mt = 0; mt < 4; ++mt)
            #pragma unroll
            for (int rh = 0; rh < 2; ++rh) { ps[mt][rh] = 0.f; pd[mt][rh] = 0.f; }
    }

    #pragma unroll
    for (int mt = 0; mt < 4; ++mt) {
        #pragma unroll
        for (int nt = 0; nt < 4; ++nt) {
            size_t r = m0 + warp_m0 + mt * 16 + g;
            size_t c = n0 + warp_n0 + nt * 8 + tq * 2;
            float v00 = acc[mt][nt][0], v01 = acc[mt][nt][1];
            float v10 = acc[mt][nt][2], v11 = acc[mt][nt][3];
            if (c_bias) {
                float cb0 = c_bias[c], cb1 = c_bias[c + 1];
                v00 += cb0; v01 += cb1; v10 += cb0; v11 += cb1;
            }
            size_t o0 = r * (size_t)Ncols + c;
            size_t o1 = (r + 8) * (size_t)Ncols + c;
            if (resid) {
                v00 += resid[o0]; v01 += resid[o0 + 1];
                v10 += resid[o1]; v11 += resid[o1 + 1];
            }
            if (att_s) {
                ps[mt][0] = fmaf(v00, as0[nt], fmaf(v01, as1[nt], ps[mt][0]));
                pd[mt][0] = fmaf(v00, ad0[nt], fmaf(v01, ad1[nt], pd[mt][0]));
                ps[mt][1] = fmaf(v10, as0[nt], fmaf(v11, as1[nt], ps[mt][1]));
                pd[mt][1] = fmaf(v10, ad0[nt], fmaf(v11, ad1[nt], pd[mt][1]));
            }
            if (Cf32) {
                *(float2*)(Cf32 + o0) = make_float2(v00, v01);
                *(float2*)(Cf32 + o1) = make_float2(v10, v11);
            }
            if (Chi) {
                split2(v00, Chi[o0], Clo[o0]);
                split2(v01, Chi[o0 + 1], Clo[o0 + 1]);
                split2(v10, Chi[o1], Clo[o1]);
                split2(v11, Chi[o1 + 1], Clo[o1 + 1]);
            }
        }
    }

    if (att_s) {
        #pragma unroll
        for (int mt = 0; mt < 4; ++mt)
            #pragma unroll
            for (int rh = 0; rh < 2; ++rh) {
                float vs = ps[mt][rh], vd = pd[mt][rh];
                vs += __shfl_xor_sync(0xFFFFFFFFu, vs, 1);
                vs += __shfl_xor_sync(0xFFFFFFFFu, vs, 2);
                vd += __shfl_xor_sync(0xFFFFFFFFu, vd, 1);
                vd += __shfl_xor_sync(0xFFFFFFFFu, vd, 2);
                if (tq == 0) {
                    size_t r = m0 + warp_m0 + mt * 16 + g + rh * 8;
                    atomicAdd(&g_asrc[r * Hh + h_att], vs);
                    atomicAdd(&g_adst[r * Hh + h_att], vd);
                }
            }
    }
}

// ---------------- CSR build ----------------
__global__ __launch_bounds__(256) void hist_kernel(const int* __restrict__ edst) {
    int e = blockIdx.x * 256 + threadIdx.x;
    atomicAdd(&g_deg[edst[e]], 1);
}
// single-block exclusive scan over 16384 degrees
__global__ __launch_bounds__(1024) void scan_kernel() {
    __shared__ int sh[1024];
    int t = threadIdx.x;
    int v[16];
    int base = t * 16, sum = 0;
    #pragma unroll
    for (int i = 0; i < 16; i++) { v[i] = g_deg[base + i]; sum += v[i]; }
    sh[t] = sum;
    __syncthreads();
    for (int off = 1; off < 1024; off <<= 1) {
        int add = (t >= off) ? sh[t - off] : 0;
        __syncthreads();
        sh[t] += add;
        __syncthreads();
    }
    int run = sh[t] - sum;
    #pragma unroll
    for (int i = 0; i < 16; i++) { g_offs[base + i] = run; run += v[i]; }
}
__global__ __launch_bounds__(256) void scatter_kernel(
    const int* __restrict__ esrc, const int* __restrict__ edst)
{
    int e = blockIdx.x * 256 + threadIdx.x;
    int d = edst[e];
    int pos = g_offs[d] + atomicAdd(&g_cursor[d], 1);
    g_csr_src[pos] = esrc[e];
}

// ---------------- fused node softmax + aggregation (no global atomics) ----
#define MAXCH 64
__global__ __launch_bounds__(256) void node_agg_kernel(
    const float* __restrict__ bias_gat)
{
    int n = blockIdx.x, t = threadIdx.x;
    int start = g_offs[n], dcount = g_deg[n];

    __shared__ unsigned s_max[Hh];
    __shared__ float s_den[Hh];
    __shared__ float s_adst[Hh], s_self[Hh], s_wself[Hh];
    __shared__ float s_w[MAXCH][Hh];
    __shared__ int s_src[MAXCH];

    if (t < Hh) {
        float as = g_asrc[n * Hh + t], ad = g_adst[n * Hh + t];
        s_adst[t] = ad;
        float self = leaky(as + ad);
        s_self[t] = self;
        s_max[t] = f2o(self);
    }
    __syncthreads();

    int et = t >> 2, h = t & 3;
    // pass 1: max
    for (int base = 0; base < dcount; base += MAXCH) {
        int e = base + et;
        if (e < dcount) {
            int s = g_csr_src[start + e];
            float logit = leaky(g_asrc[s * Hh + h] + s_adst[h]);
            atomicMax(&s_max[h], f2o(logit));
        }
    }
    __syncthreads();
    if (t < Hh) s_den[t] = expf(s_self[t] - o2f(s_max[t]));
    __syncthreads();
    // pass 2: denom
    for (int base = 0; base < dcount; base += MAXCH) {
        int e = base + et;
        if (e < dcount) {
            int s = g_csr_src[start + e];
            float logit = leaky(g_asrc[s * Hh + h] + s_adst[h]);
            atomicAdd(&s_den[h], expf(logit - o2f(s_max[h])));
        }
    }
    __syncthreads();
    if (t < Hh)
        s_wself[t] = expf(s_self[t] - o2f(s_max[t])) / s_den[t] * (1.0f / Hh);
    __syncthreads();

    // pass 3: aggregate (self + edges)
    const float* xn = g_xh + (size_t)n * HD;
    float acc = 0.f;
    #pragma unroll
    for (int hh = 0; hh < Hh; hh++) acc = fmaf(s_wself[hh], xn[hh * Cc + t], acc);

    for (int base = 0; base < dcount; base += MAXCH) {
        int cnt = min(MAXCH, dcount - base);
        int e = base + et;
        if (e < dcount) {
            int s = g_csr_src[start + e];
            float logit = leaky(g_asrc[s * Hh + h] + s_adst[h]);
            s_w[et][h] = expf(logit - o2f(s_max[h])) / s_den[h] * (1.0f / Hh);
            if (h == 0) s_src[et] = s;
        }
        __syncthreads();
        for (int e2 = 0; e2 < cnt; e2++) {
            const float* xr = g_xh + (size_t)s_src[e2] * HD;
            #pragma unroll
            for (int hh = 0; hh < Hh; hh++)
                acc = fmaf(s_w[e2][hh], xr[hh * Cc + t], acc);
        }
        __syncthreads();
    }

    float v = acc + bias_gat[t];
    split2(v, g_agg_hi[(size_t)n * Dm + t], g_agg_lo[(size_t)n * Dm + t]);
}

// ---------------- launch ----------------
extern "C" void kernel_launch(void* const* d_in, const int* in_sizes, int n_in,
                              void* d_out, int out_size)
{
    const float* inputs   = (const float*)d_in[0];
    const int*   eidx     = (const int*)d_in[1];
    const float* ln_gamma = (const float*)d_in[2];
    const float* ln_beta  = (const float*)d_in[3];
    const float* W1       = (const float*)d_in[4];
    const float* b1       = (const float*)d_in[5];
    const float* W_gat    = (const float*)d_in[6];
    const float* att_src  = (const float*)d_in[7];
    const float* att_dst  = (const float*)d_in[8];
    const float* bias_gat = (const float*)d_in[9];
    const float* W2       = (const float*)d_in[10];
    const float* b2       = (const float*)d_in[11];
    float*       out      = (float*)d_out;

    const int* esrc = eidx;
    const int* edst = eidx + Ee;

    __nv_bfloat16 *xln_hi, *xln_lo, *gnn_hi, *gnn_lo, *agg_hi, *agg_lo;
    __nv_bfloat16 *w1_hi, *w1_lo, *wg_hi, *wg_lo, *w2_hi, *w2_lo;
    float *xh;
    cudaGetSymbolAddress((void**)&xln_hi, g_xln_hi);
    cudaGetSymbolAddress((void**)&xln_lo, g_xln_lo);
    cudaGetSymbolAddress((void**)&gnn_hi, g_gnn_hi);
    cudaGetSymbolAddress((void**)&gnn_lo, g_gnn_lo);
    cudaGetSymbolAddress((void**)&agg_hi, g_agg_hi);
    cudaGetSymbolAddress((void**)&agg_lo, g_agg_lo);
    cudaGetSymbolAddress((void**)&w1_hi, g_w1_hi);
    cudaGetSymbolAddress((void**)&w1_lo, g_w1_lo);
    cudaGetSymbolAddress((void**)&wg_hi, g_wg_hi);
    cudaGetSymbolAddress((void**)&wg_lo, g_wg_lo);
    cudaGetSymbolAddress((void**)&w2_hi, g_w2_hi);
    cudaGetSymbolAddress((void**)&w2_lo, g_w2_lo);
    cudaGetSymbolAddress((void**)&xh,  g_xh);

    cudaFuncSetAttribute(gemm_mma, cudaFuncAttributeMaxDynamicSharedMemorySize, GEMM_SMEM);

    // launch order chosen so the 6th kernel (-s 5 -c 1) is the big GEMM (xh)
    // 0: zero (deg/cursor/asrc/adst)
    zero_kernel<<<(Nn_NODES * Hh) / 256, 256>>>();
    // 1: weight splits (fused)
    splitW_kernel<<<(HD * Dm) / 256, 256>>>(W1, W_gat, W2);
    // 2: LayerNorm
    ln_kernel<<<Nn_NODES / 8, 256>>>(inputs, ln_gamma, ln_beta);
    // 3: gnn = xln @ W1^T + b1
    gemm_mma<<<dim3(Dm / 128, Nn_NODES / 128), 256, GEMM_SMEM>>>(
        xln_hi, xln_lo, w1_hi, w1_lo, Dm, b1, nullptr, nullptr, gnn_hi, gnn_lo,
        nullptr, nullptr);
    // 4: degree histogram
    hist_kernel<<<Ee / 256, 256>>>(edst);
    // 5: xh = gnn @ W_gat^T  (+ fused attention dots)   <-- ncu capture target
    gemm_mma<<<dim3(HD / 128, Nn_NODES / 128), 256, GEMM_SMEM>>>(
        gnn_hi, gnn_lo, wg_hi, wg_lo, HD, nullptr, nullptr, xh, nullptr, nullptr,
        att_src, att_dst);
    // 6: scan
    scan_kernel<<<1, 1024>>>();
    // 7: scatter
    scatter_kernel<<<Ee / 256, 256>>>(esrc, edst);
    // 8: fused segment softmax + aggregation
    node_agg_kernel<<<Nn_NODES, 256>>>(bias_gat);
    // 9: out = (agg + bias_gat) @ W2^T + b2 + inputs
    gemm_mma<<<dim3(Dm / 128, Nn_NODES / 128), 256, GEMM_SMEM>>>(
        agg_hi, agg_lo, w2_hi, w2_lo, Dm, b2, inputs, out, nullptr, nullptr,
        nullptr, nullptr);
}

// round 7
// speedup vs baseline: 2.2725x; 1.0641x over previous
#include <cuda_runtime.h>
#include <cuda_bf16.h>
#include <cstdint>

// ---------------- problem constants ----------------
#define Nn_NODES 16384      // B*L
#define Dm 256              // d_model
#define Hh 4                // heads
#define Cc 256              // per-head channels
#define HD (Hh*Cc)          // 1024
#define Ee 65536            // edges
#define NEG_SLOPE 0.2f
#define LN_EPS 1e-6f

// ---------------- device scratch ----------------
__device__ __nv_bfloat16 g_xln_hi[Nn_NODES * Dm];
__device__ __nv_bfloat16 g_xln_lo[Nn_NODES * Dm];
__device__ __nv_bfloat16 g_gnn_hi[Nn_NODES * Dm];
__device__ __nv_bfloat16 g_gnn_lo[Nn_NODES * Dm];
__device__ __nv_bfloat16 g_agg_hi[Nn_NODES * Dm];
__device__ __nv_bfloat16 g_agg_lo[Nn_NODES * Dm];
__device__ __nv_bfloat16 g_w1_hi[Dm * Dm],  g_w1_lo[Dm * Dm];
__device__ __nv_bfloat16 g_wg_hi[HD * Dm],  g_wg_lo[HD * Dm];
__device__ __nv_bfloat16 g_w2_hi[Dm * Dm],  g_w2_lo[Dm * Dm];
__device__ float    g_xh   [Nn_NODES * HD];
__device__ float    g_asrc [Nn_NODES * Hh];
__device__ float    g_adst [Nn_NODES * Hh];
// CSR structures
__device__ int g_deg   [Nn_NODES];
__device__ int g_offs  [Nn_NODES];
__device__ int g_cursor[Nn_NODES];
__device__ int g_csr_src[Ee];

// ---------------- helpers ----------------
__device__ __forceinline__ float leaky(float x) { return x > 0.0f ? x : NEG_SLOPE * x; }
__device__ __forceinline__ unsigned f2o(float f) {
    unsigned u = __float_as_uint(f);
    return (u & 0x80000000u) ? ~u : (u | 0x80000000u);
}
__device__ __forceinline__ float o2f(unsigned u) {
    return (u & 0x80000000u) ? __uint_as_float(u & 0x7FFFFFFFu) : __uint_as_float(~u);
}
__device__ __forceinline__ float warp_sum(float v) {
    #pragma unroll
    for (int o = 16; o > 0; o >>= 1) v += __shfl_xor_sync(0xFFFFFFFFu, v, o);
    return v;
}
__device__ __forceinline__ void split2(float v, __nv_bfloat16& h, __nv_bfloat16& l) {
    h = __float2bfloat16(v);
    l = __float2bfloat16(v - __bfloat162float(h));
}
__device__ __forceinline__ uint32_t smem_to_u32(const void* p) {
    uint32_t a;
    asm("{ .reg .u64 t; cvta.to.shared.u64 t, %1; cvt.u32.u64 %0, t; }"
        : "=r"(a) : "l"(p));
    return a;
}

// ---------------- mma / ldmatrix / cp.async PTX (sm_80-compatible) --------
#define LDM4(r, addr) \
    asm volatile("ldmatrix.sync.aligned.m8n8.x4.shared.b16 {%0,%1,%2,%3}, [%4];" \
        : "=r"((r)[0]), "=r"((r)[1]), "=r"((r)[2]), "=r"((r)[3]) : "r"(addr))

#define MMA_BF16(c, a, b0, b1) \
    asm volatile("mma.sync.aligned.m16n8k16.row.col.f32.bf16.bf16.f32 " \
        "{%0,%1,%2,%3}, {%4,%5,%6,%7}, {%8,%9}, {%0,%1,%2,%3};" \
        : "+f"((c)[0]), "+f"((c)[1]), "+f"((c)[2]), "+f"((c)[3]) \
        : "r"((a)[0]), "r"((a)[1]), "r"((a)[2]), "r"((a)[3]), "r"(b0), "r"(b1))

#define CP_ASYNC16(dst, src) \
    asm volatile("cp.async.cg.shared.global [%0], [%1], 16;" \
        :: "r"(dst), "l"(src) : "memory")
#define CP_COMMIT() asm volatile("cp.async.commit_group;" ::: "memory")
#define CP_WAIT1()  asm volatile("cp.async.wait_group 1;" ::: "memory")
#define CP_WAIT0()  asm volatile("cp.async.wait_group 0;" ::: "memory")

// ---------------- zero kernel (deg, cursor, asrc, adst) ----------------
__global__ __launch_bounds__(256) void zero_kernel() {
    int i = blockIdx.x * 256 + threadIdx.x;     // grid covers 65536
    if (i < Nn_NODES) { g_deg[i] = 0; g_cursor[i] = 0; }
    g_asrc[i] = 0.f;
    g_adst[i] = 0.f;
}

// ---------------- fused weight split ----------------
__global__ __launch_bounds__(256) void splitW_kernel(
    const float* __restrict__ W1, const float* __restrict__ Wg,
    const float* __restrict__ W2)
{
    int i = blockIdx.x * 256 + threadIdx.x;     // grid covers HD*Dm = 262144
    if (i < Dm * Dm) {
        split2(W1[i], g_w1_hi[i], g_w1_lo[i]);
        split2(W2[i], g_w2_hi[i], g_w2_lo[i]);
    }
    split2(Wg[i], g_wg_hi[i], g_wg_lo[i]);
}

// ---------------- LayerNorm: warp per row, float4 ----------------
__global__ __launch_bounds__(256) void ln_kernel(
    const float* __restrict__ x, const float* __restrict__ gamma,
    const float* __restrict__ beta)
{
    int row  = blockIdx.x * 8 + (threadIdx.x >> 5);
    int lane = threadIdx.x & 31;
    const float* xr = x + (size_t)row * Dm;
    float4 v0 = *(const float4*)(xr + lane * 4);
    float4 v1 = *(const float4*)(xr + 128 + lane * 4);
    float s  = v0.x + v0.y + v0.z + v0.w + v1.x + v1.y + v1.z + v1.w;
    float s2 = v0.x*v0.x + v0.y*v0.y + v0.z*v0.z + v0.w*v0.w
             + v1.x*v1.x + v1.y*v1.y + v1.z*v1.z + v1.w*v1.w;
    s = warp_sum(s);
    s2 = warp_sum(s2);
    float mu   = s * (1.0f / Dm);
    float var  = s2 * (1.0f / Dm) - mu * mu;
    float rstd = rsqrtf(var + LN_EPS);

    float o[8];
    float4 gm0 = *(const float4*)(gamma + lane * 4);
    float4 gm1 = *(const float4*)(gamma + 128 + lane * 4);
    float4 bt0 = *(const float4*)(beta + lane * 4);
    float4 bt1 = *(const float4*)(beta + 128 + lane * 4);
    o[0] = (v0.x - mu) * rstd * gm0.x + bt0.x;
    o[1] = (v0.y - mu) * rstd * gm0.y + bt0.y;
    o[2] = (v0.z - mu) * rstd * gm0.z + bt0.z;
    o[3] = (v0.w - mu) * rstd * gm0.w + bt0.w;
    o[4] = (v1.x - mu) * rstd * gm1.x + bt1.x;
    o[5] = (v1.y - mu) * rstd * gm1.y + bt1.y;
    o[6] = (v1.z - mu) * rstd * gm1.z + bt1.z;
    o[7] = (v1.w - mu) * rstd * gm1.w + bt1.w;
    #pragma unroll
    for (int i = 0; i < 8; i++) {
        size_t idx = (size_t)row * Dm + (i < 4 ? lane * 4 + i : 128 + lane * 4 + i - 4);
        split2(o[i], g_xln_hi[idx], g_xln_lo[idx]);
    }
}

// ---------------- bf16x3 HMMA GEMM, pass-major virtual chunks ------------
// 12 chunks: pass 0 (Ahi*Bhi) k0..3, pass 1 (Ahi*Blo) k0..3, pass 2 (Alo*Bhi).
// Stage = 32KB (one A buffer + one B buffer), 3 stages = 96KB -> 2 CTA/SM.
#define ST_STRIDE 32768
#define O_B 16384
#define GEMM_SMEM (3 * ST_STRIDE)

__global__ __launch_bounds__(256, 2) void gemm_mma(
    const __nv_bfloat16* __restrict__ Ahi, const __nv_bfloat16* __restrict__ Alo,
    const __nv_bfloat16* __restrict__ Bhi, const __nv_bfloat16* __restrict__ Blo,
    int Ncols, const float* __restrict__ c_bias, const float* __restrict__ resid,
    float* __restrict__ Cf32, __nv_bfloat16* __restrict__ Chi,
    __nv_bfloat16* __restrict__ Clo,
    const float* __restrict__ att_s, const float* __restrict__ att_d)
{
    extern __shared__ char smem[];
    uint32_t sb = smem_to_u32(smem);
    const int tid = threadIdx.x, lane = tid & 31, wid = tid >> 5;
    const int warp_m0 = (wid >> 2) * 64;
    const int warp_n0 = (wid & 3) * 32;
    const size_t m0 = (size_t)blockIdx.y * 128;
    const size_t n0 = (size_t)blockIdx.x * 128;

    float acc[4][4][4];
    #pragma unroll
    for (int i = 0; i < 4; i++)
        #pragma unroll
        for (int j = 0; j < 4; j++)
            #pragma unroll
            for (int k = 0; k < 4; k++) acc[i][j][k] = 0.f;

    const int arow = lane & 15;
    const int akb  = (lane >> 4) << 4;
    const int brl  = ((lane >> 4) << 3) | (lane & 7);
    const int bkb  = ((lane >> 3) & 1) << 4;
    const uint32_t aswz = (uint32_t)(arow & 7) << 4;
    const uint32_t bswz = (uint32_t)(lane & 7) << 4;

    auto issue = [&](int stage, int chunk) {
        int p   = chunk >> 2;
        int kc0 = (chunk & 3) * 64;
        const __nv_bfloat16* Ap = (p == 2) ? Alo : Ahi;
        const __nv_bfloat16* Bp = (p == 1) ? Blo : Bhi;
        uint32_t s0 = sb + stage * ST_STRIDE;
        #pragma unroll
        for (int it = 0; it < 4; ++it) {
            int idx = tid + it * 256;
            int row = idx >> 3, c16 = idx & 7;
            uint32_t off = (uint32_t)row * 128 + c16 * 16;
            off ^= ((uint32_t)(row & 7)) << 4;           // SW128
            CP_ASYNC16(s0 + off,       Ap + (m0 + row) * 256 + kc0 + c16 * 8);
            CP_ASYNC16(s0 + O_B + off, Bp + (n0 + row) * 256 + kc0 + c16 * 8);
        }
    };

    issue(0, 0); CP_COMMIT();
    issue(1, 1); CP_COMMIT();

    for (int c = 0; c < 12; ++c) {
        if (c < 11) { CP_WAIT1(); } else { CP_WAIT0(); }
        __syncthreads();
        if (c + 2 < 12) { issue((c + 2) % 3, c + 2); CP_COMMIT(); }

        uint32_t st = sb + (c % 3) * ST_STRIDE;
        #pragma unroll
        for (int k16 = 0; k16 < 4; ++k16) {
            int kbyte = k16 * 32;
            uint32_t af[4][4], bf[2][4];
            #pragma unroll
            for (int mt = 0; mt < 4; ++mt) {
                uint32_t ad = st +
                    (uint32_t)(warp_m0 + mt * 16 + arow) * 128 + kbyte + akb;
                LDM4(af[mt], ad ^ aswz);
            }
            #pragma unroll
            for (int g2 = 0; g2 < 2; ++g2) {
                uint32_t bd = st + O_B +
                    (uint32_t)(warp_n0 + g2 * 16 + brl) * 128 + kbyte + bkb;
                LDM4(bf[g2], bd ^ bswz);
            }
            #pragma unroll
            for (int mt = 0; mt < 4; ++mt)
                #pragma unroll
                for (int nt = 0; nt < 4; ++nt) {
                    int g2 = nt >> 1, p2 = (nt & 1) << 1;
                    MMA_BF16(acc[mt][nt], af[mt], bf[g2][p2], bf[g2][p2 + 1]);
                }
        }
        __syncthreads();
    }

    // ---- epilogue ----
    const int g = lane >> 2, tq = lane & 3;

    const int h_att = (int)(n0 >> 8);
    float as0[4], as1[4], ad0[4], ad1[4];
    float ps[4][2], pd[4][2];
    if (att_s) {
        int cih0 = (int)(n0 & 255) + warp_n0 + tq * 2;
        #pragma unroll
        for (int nt = 0; nt < 4; ++nt) {
            int cih = cih0 + nt * 8;
            as0[nt] = att_s[h_att * Cc + cih];
            as1[nt] = att_s[h_att * Cc + cih + 1];
            ad0[nt] = att_d[h_att * Cc + cih];
            ad1[nt] = att_d[h_att * Cc + cih + 1];
        }
        #pragma unroll
        for (int mt = 0; mt < 4; ++mt)
            #pragma unroll
            for (int rh = 0; rh < 2; ++rh) { ps[mt][rh] = 0.f; pd[mt][rh] = 0.f; }
    }

    #pragma unroll
    for (int mt = 0; mt < 4; ++mt) {
        #pragma unroll
        for (int nt = 0; nt < 4; ++nt) {
            size_t r = m0 + warp_m0 + mt * 16 + g;
            size_t c = n0 + warp_n0 + nt * 8 + tq * 2;
            float v00 = acc[mt][nt][0], v01 = acc[mt][nt][1];
            float v10 = acc[mt][nt][2], v11 = acc[mt][nt][3];
            if (c_bias) {
                float cb0 = c_bias[c], cb1 = c_bias[c + 1];
                v00 += cb0; v01 += cb1; v10 += cb0; v11 += cb1;
            }
            size_t o0 = r * (size_t)Ncols + c;
            size_t o1 = (r + 8) * (size_t)Ncols + c;
            if (resid) {
                v00 += resid[o0]; v01 += resid[o0 + 1];
                v10 += resid[o1]; v11 += resid[o1 + 1];
            }
            if (att_s) {
                ps[mt][0] = fmaf(v00, as0[nt], fmaf(v01, as1[nt], ps[mt][0]));
                pd[mt][0] = fmaf(v00, ad0[nt], fmaf(v01, ad1[nt], pd[mt][0]));
                ps[mt][1] = fmaf(v10, as0[nt], fmaf(v11, as1[nt], ps[mt][1]));
                pd[mt][1] = fmaf(v10, ad0[nt], fmaf(v11, ad1[nt], pd[mt][1]));
            }
            if (Cf32) {
                *(float2*)(Cf32 + o0) = make_float2(v00, v01);
                *(float2*)(Cf32 + o1) = make_float2(v10, v11);
            }
            if (Chi) {
                split2(v00, Chi[o0], Clo[o0]);
                split2(v01, Chi[o0 + 1], Clo[o0 + 1]);
                split2(v10, Chi[o1], Clo[o1]);
                split2(v11, Chi[o1 + 1], Clo[o1 + 1]);
            }
        }
    }

    if (att_s) {
        #pragma unroll
        for (int mt = 0; mt < 4; ++mt)
            #pragma unroll
            for (int rh = 0; rh < 2; ++rh) {
                float vs = ps[mt][rh], vd = pd[mt][rh];
                vs += __shfl_xor_sync(0xFFFFFFFFu, vs, 1);
                vs += __shfl_xor_sync(0xFFFFFFFFu, vs, 2);
                vd += __shfl_xor_sync(0xFFFFFFFFu, vd, 1);
                vd += __shfl_xor_sync(0xFFFFFFFFu, vd, 2);
                if (tq == 0) {
                    size_t r = m0 + warp_m0 + mt * 16 + g + rh * 8;
                    atomicAdd(&g_asrc[r * Hh + h_att], vs);
                    atomicAdd(&g_adst[r * Hh + h_att], vd);
                }
            }
    }
}

// ---------------- CSR build ----------------
__global__ __launch_bounds__(256) void hist_kernel(const int* __restrict__ edst) {
    int e = blockIdx.x * 256 + threadIdx.x;
    atomicAdd(&g_deg[edst[e]], 1);
}
__global__ __launch_bounds__(1024) void scan_kernel() {
    __shared__ int sh[1024];
    int t = threadIdx.x;
    int v[16];
    int base = t * 16, sum = 0;
    #pragma unroll
    for (int i = 0; i < 16; i++) { v[i] = g_deg[base + i]; sum += v[i]; }
    sh[t] = sum;
    __syncthreads();
    for (int off = 1; off < 1024; off <<= 1) {
        int add = (t >= off) ? sh[t - off] : 0;
        __syncthreads();
        sh[t] += add;
        __syncthreads();
    }
    int run = sh[t] - sum;
    #pragma unroll
    for (int i = 0; i < 16; i++) { g_offs[base + i] = run; run += v[i]; }
}
__global__ __launch_bounds__(256) void scatter_kernel(
    const int* __restrict__ esrc, const int* __restrict__ edst)
{
    int e = blockIdx.x * 256 + threadIdx.x;
    int d = edst[e];
    int pos = g_offs[d] + atomicAdd(&g_cursor[d], 1);
    g_csr_src[pos] = esrc[e];
}

// ---------------- fused node softmax + aggregation --------------------
// Chunk-0 logits cached in smem; only one gather round for typical degrees.
#define MAXCH 64
__global__ __launch_bounds__(256) void node_agg_kernel(
    const float* __restrict__ bias_gat)
{
    int n = blockIdx.x, t = threadIdx.x;
    int start = g_offs[n], dcount = g_deg[n];

    __shared__ unsigned s_max[Hh];
    __shared__ float s_den[Hh];
    __shared__ float s_adst[Hh], s_self[Hh], s_wself[Hh];
    __shared__ float s_w[MAXCH][Hh];
    __shared__ int s_src[MAXCH];

    if (t < Hh) {
        float as = g_asrc[n * Hh + t], ad = g_adst[n * Hh + t];
        s_adst[t] = ad;
        float self = leaky(as + ad);
        s_self[t] = self;
        s_max[t] = f2o(self);
        s_den[t] = 0.f;
    }
    __syncthreads();

    int et = t >> 2, h = t & 3;
    int cnt0 = min(dcount, MAXCH);

    // pass 1: logits (cache chunk 0) + running max
    if (et < cnt0) {
        int s = g_csr_src[start + et];
        float logit = leaky(g_asrc[s * Hh + h] + s_adst[h]);
        s_w[et][h] = logit;
        if (h == 0) s_src[et] = s;
        atomicMax(&s_max[h], f2o(logit));
    }
    for (int base = MAXCH; base < dcount; base += MAXCH) {
        int e = base + et;
        if (e < dcount) {
            int s = g_csr_src[start + e];
            float logit = leaky(g_asrc[s * Hh + h] + s_adst[h]);
            atomicMax(&s_max[h], f2o(logit));
        }
    }
    __syncthreads();

    float m_h = o2f(s_max[h]);
    // pass 2: denom (chunk 0 from cache)
    if (et < cnt0) atomicAdd(&s_den[h], expf(s_w[et][h] - m_h));
    for (int base = MAXCH; base < dcount; base += MAXCH) {
        int e = base + et;
        if (e < dcount) {
            int s = g_csr_src[start + e];
            float logit = leaky(g_asrc[s * Hh + h] + s_adst[h]);
            atomicAdd(&s_den[h], expf(logit - m_h));
        }
    }
    __syncthreads();
    if (t < Hh) {
        float eself = expf(s_self[t] - o2f(s_max[t]));
        float denom = s_den[t] + eself;
        s_den[t] = denom;
        s_wself[t] = eself / denom * (1.0f / Hh);
    }
    __syncthreads();
    // convert cached logits -> weights in place
    if (et < cnt0)
        s_w[et][h] = expf(s_w[et][h] - m_h) / s_den[h] * (1.0f / Hh);
    __syncthreads();

    // aggregate (self + cached chunk 0)
    const float* xn = g_xh + (size_t)n * HD;
    float acc = 0.f;
    #pragma unroll
    for (int hh = 0; hh < Hh; hh++) acc = fmaf(s_wself[hh], xn[hh * Cc + t], acc);

    for (int e2 = 0; e2 < cnt0; e2++) {
        const float* xr = g_xh + (size_t)s_src[e2] * HD;
        #pragma unroll
        for (int hh = 0; hh < Hh; hh++)
            acc = fmaf(s_w[e2][hh], xr[hh * Cc + t], acc);
    }

    // remaining chunks (recompute weights)
    for (int base = MAXCH; base < dcount; base += MAXCH) {
        int cnt = min(MAXCH, dcount - base);
        __syncthreads();
        if (base + et < dcount) {
            int s = g_csr_src[start + base + et];
            float logit = leaky(g_asrc[s * Hh + h] + s_adst[h]);
            s_w[et][h] = expf(logit - m_h) / s_den[h] * (1.0f / Hh);
            if (h == 0) s_src[et] = s;
        }
        __syncthreads();
        for (int e2 = 0; e2 < cnt; e2++) {
            const float* xr = g_xh + (size_t)s_src[e2] * HD;
            #pragma unroll
            for (int hh = 0; hh < Hh; hh++)
                acc = fmaf(s_w[e2][hh], xr[hh * Cc + t], acc);
        }
    }

    float v = acc + bias_gat[t];
    split2(v, g_agg_hi[(size_t)n * Dm + t], g_agg_lo[(size_t)n * Dm + t]);
}

// ---------------- launch ----------------
extern "C" void kernel_launch(void* const* d_in, const int* in_sizes, int n_in,
                              void* d_out, int out_size)
{
    const float* inputs   = (const float*)d_in[0];
    const int*   eidx     = (const int*)d_in[1];
    const float* ln_gamma = (const float*)d_in[2];
    const float* ln_beta  = (const float*)d_in[3];
    const float* W1       = (const float*)d_in[4];
    const float* b1       = (const float*)d_in[5];
    const float* W_gat    = (const float*)d_in[6];
    const float* att_src  = (const float*)d_in[7];
    const float* att_dst  = (const float*)d_in[8];
    const float* bias_gat = (const float*)d_in[9];
    const float* W2       = (const float*)d_in[10];
    const float* b2       = (const float*)d_in[11];
    float*       out      = (float*)d_out;

    const int* esrc = eidx;
    const int* edst = eidx + Ee;

    __nv_bfloat16 *xln_hi, *xln_lo, *gnn_hi, *gnn_lo, *agg_hi, *agg_lo;
    __nv_bfloat16 *w1_hi, *w1_lo, *wg_hi, *wg_lo, *w2_hi, *w2_lo;
    float *xh;
    cudaGetSymbolAddress((void**)&xln_hi, g_xln_hi);
    cudaGetSymbolAddress((void**)&xln_lo, g_xln_lo);
    cudaGetSymbolAddress((void**)&gnn_hi, g_gnn_hi);
    cudaGetSymbolAddress((void**)&gnn_lo, g_gnn_lo);
    cudaGetSymbolAddress((void**)&agg_hi, g_agg_hi);
    cudaGetSymbolAddress((void**)&agg_lo, g_agg_lo);
    cudaGetSymbolAddress((void**)&w1_hi, g_w1_hi);
    cudaGetSymbolAddress((void**)&w1_lo, g_w1_lo);
    cudaGetSymbolAddress((void**)&wg_hi, g_wg_hi);
    cudaGetSymbolAddress((void**)&wg_lo, g_wg_lo);
    cudaGetSymbolAddress((void**)&w2_hi, g_w2_hi);
    cudaGetSymbolAddress((void**)&w2_lo, g_w2_lo);
    cudaGetSymbolAddress((void**)&xh,  g_xh);

    cudaFuncSetAttribute(gemm_mma, cudaFuncAttributeMaxDynamicSharedMemorySize, GEMM_SMEM);

    // launch order keeps the big GEMM (xh) at ncu capture index 5
    zero_kernel<<<(Nn_NODES * Hh) / 256, 256>>>();
    splitW_kernel<<<(HD * Dm) / 256, 256>>>(W1, W_gat, W2);
    ln_kernel<<<Nn_NODES / 8, 256>>>(inputs, ln_gamma, ln_beta);
    gemm_mma<<<dim3(Dm / 128, Nn_NODES / 128), 256, GEMM_SMEM>>>(
        xln_hi, xln_lo, w1_hi, w1_lo, Dm, b1, nullptr, nullptr, gnn_hi, gnn_lo,
        nullptr, nullptr);
    hist_kernel<<<Ee / 256, 256>>>(edst);
    gemm_mma<<<dim3(HD / 128, Nn_NODES / 128), 256, GEMM_SMEM>>>(
        gnn_hi, gnn_lo, wg_hi, wg_lo, HD, nullptr, nullptr, xh, nullptr, nullptr,
        att_src, att_dst);
    scan_kernel<<<1, 1024>>>();
    scatter_kernel<<<Ee / 256, 256>>>(esrc, edst);
    node_agg_kernel<<<Nn_NODES, 256>>>(bias_gat);
    gemm_mma<<<dim3(Dm / 128, Nn_NODES / 128), 256, GEMM_SMEM>>>(
        agg_hi, agg_lo, w2_hi, w2_lo, Dm, b2, inputs, out, nullptr, nullptr,
        nullptr, nullptr);
}